// round 6
// baseline (speedup 1.0000x reference)
#include <cuda_runtime.h>
#include <math.h>

#define T_STEPS 10
#define B_GR    8
#define NPG     1080
#define N_NODES 8640
#define TN      86400
#define DEG     16

// ---------------- scratch ----------------
__device__ float g_bufA[(size_t)TN * 256];
__device__ float g_bufB[(size_t)TN * 256];
__device__ float g_z[TN * 16];
__device__ float g_emb[T_STEPS * B_GR * 8];
__device__ float g_uv[32];
__device__ int   g_lsrc[N_NODES * 16];

// ---------------- fast exp for x <= 0 (FMA pipe only) ----------------
__device__ __forceinline__ float exp_neg(float x) {
    x = fmaxf(x, -87.0f);
    const float L2E = 1.4426950408889634f;
    float z = fmaf(x, L2E, 12582912.0f);
    int   ei = __float_as_int(z);
    float n = z - 12582912.0f;
    float f = fmaf(x, L2E, -n);
    float r = fmaf(1.5403530e-4f, f, 1.3333558e-3f);
    r = fmaf(r, f, 9.6181291e-3f);
    r = fmaf(r, f, 5.5504109e-2f);
    r = fmaf(r, f, 2.4022651e-1f);
    r = fmaf(r, f, 6.9314718e-1f);
    r = fmaf(r, f, 1.0f);
    float s = __int_as_float((ei + 127) << 23);
    return r * s;
}
__device__ __forceinline__ float elu_f(float v) { return v > 0.f ? v : exp_neg(v) - 1.f; }
__device__ __forceinline__ float lrelu(float e) { return e >= 0.f ? e : 0.2f * e; }

// ---------------- setup: lsrc localization + W1-folded attention vectors ----------------
__global__ void setup_kernel(const int* __restrict__ src, const float* __restrict__ W1,
                             const float* __restrict__ as1, const float* __restrict__ ad1) {
    int bid = blockIdx.x;
    if (bid < 540) {
        int i = bid * 256 + threadIdx.x;          // 540*256 == N_NODES*16
        int b = i / (NPG * 16);
        g_lsrc[i] = src[i] - b * NPG;
    } else {
        int tid = threadIdx.x;
        if (tid < 32) {
            int d = tid >> 4, h = (tid >> 1) & 7, f = tid & 1;
            const float* a = d ? ad1 : as1;
            float s = 0.f;
            #pragma unroll
            for (int c = 0; c < 64; c++) s += W1[f * 512 + h * 64 + c] * a[h * 64 + c];
            g_uv[tid] = s;
        }
    }
}

// ---------------- layer 1 fully fused: x -> z[TN,16] ----------------
__global__ __launch_bounds__(1024, 1)
void l1_fused(const float* __restrict__ x) {
    extern __shared__ float sm[];
    float* xs   = sm;                 // NPG*2
    float* es_s = xs + NPG * 2;       // NPG*8
    float* ed_s = es_s + NPG * 8;     // NPG*8
    __shared__ float uvS[32];
    int tb = blockIdx.x;
    int b = tb & 7, t = tb >> 3;
    int base = t * N_NODES + b * NPG;
    int tid = threadIdx.x;
    if (tid < 32) uvS[tid] = g_uv[tid];
    for (int i = tid; i < NPG * 2; i += blockDim.x) xs[i] = x[(size_t)base * 2 + i];
    __syncthreads();
    for (int task = tid; task < NPG * 8; task += blockDim.x) {
        int n = task >> 3, h = task & 7;
        float x0 = xs[n * 2], x1 = xs[n * 2 + 1];
        es_s[task] = fmaf(x0, uvS[h * 2], x1 * uvS[h * 2 + 1]);
        ed_s[task] = fmaf(x0, uvS[16 + h * 2], x1 * uvS[16 + h * 2 + 1]);
    }
    __syncthreads();
    for (int task = tid; task < NPG * 8; task += blockDim.x) {
        int n = task >> 3, h = task & 7;
        const int4* ls4 = (const int4*)(g_lsrc + ((size_t)b * NPG + n) * 16);
        int4 iA = ls4[0], iB = ls4[1], iC = ls4[2], iD = ls4[3];
        int idxs[16] = {iA.x, iA.y, iA.z, iA.w, iB.x, iB.y, iB.z, iB.w,
                        iC.x, iC.y, iC.z, iC.w, iD.x, iD.y, iD.z, iD.w};
        float ed = ed_s[task];
        float ev[17];
        float m = -1e30f;
        #pragma unroll
        for (int k = 0; k < 16; k++) {
            float e = lrelu(es_s[idxs[k] * 8 + h] + ed);
            ev[k] = e; m = fmaxf(m, e);
        }
        { float e = lrelu(es_s[task] + ed); ev[16] = e; m = fmaxf(m, e); }
        float ssum = 0.f;
        #pragma unroll
        for (int k = 0; k < 17; k++) { float v = exp_neg(ev[k] - m); ev[k] = v; ssum += v; }
        float inv = 1.f / (ssum + 1e-16f);
        float z0 = 0.f, z1 = 0.f;
        #pragma unroll
        for (int k = 0; k < 16; k++) {
            float a = ev[k] * inv;
            z0 = fmaf(a, xs[idxs[k] * 2], z0);
            z1 = fmaf(a, xs[idxs[k] * 2 + 1], z1);
        }
        {
            float a = ev[16] * inv;
            z0 = fmaf(a, xs[n * 2], z0);
            z1 = fmaf(a, xs[n * 2 + 1], z1);
        }
        *(float2*)&g_z[(size_t)(base + n) * 16 + h * 2] = make_float2(z0, z1);
    }
}

// ---------------- L2 GEMM, double-buffered, fused layer-1 expansion ----------------
__global__ __launch_bounds__(256, 2)
void l1gemm(const float* __restrict__ W1, const float* __restrict__ b1,
            const float* __restrict__ W, float* __restrict__ C, int Nc) {
    __shared__ float As[2][16][136];
    __shared__ float Ws[2][16][136];
    __shared__ float zs[128][16];
    __shared__ float W1s[1024];
    __shared__ float b1s[512];
    const int tid = threadIdx.x;
    const int tx = tid & 15, ty = tid >> 4;
    const int rb = blockIdx.y * 128, cb = blockIdx.x * 128;
    const int arow = tid >> 1, ap = tid & 1;
    const int wk = tid >> 5, wc = tid & 31;
    for (int i = tid; i < 1024; i += 256) W1s[i] = W1[i];
    for (int i = tid; i < 512; i += 256) b1s[i] = b1[i];
    for (int i = tid; i < 512; i += 256)
        *(float4*)&zs[i >> 2][(i & 3) * 4] = *(const float4*)(g_z + (size_t)(rb + (i >> 2)) * 16 + (i & 3) * 4);
    __syncthreads();
    {
        int kk = ap * 8, h = kk >> 6;
        float za = zs[arow][h * 2], zb = zs[arow][h * 2 + 1];
        #pragma unroll
        for (int j = 0; j < 8; j++) {
            int k = kk + j;
            As[0][ap * 8 + j][arow] = elu_f(fmaf(za, W1s[k], fmaf(zb, W1s[512 + k], b1s[k])));
        }
        *(float4*)&Ws[0][wk][wc * 4]     = *(const float4*)(W + (size_t)wk * Nc + cb + wc * 4);
        *(float4*)&Ws[0][wk + 8][wc * 4] = *(const float4*)(W + (size_t)(wk + 8) * Nc + cb + wc * 4);
    }
    __syncthreads();
    float acc[8][8] = {};
    for (int k0 = 0; k0 < 512; k0 += 16) {
        int p = (k0 >> 4) & 1;
        float av[8];
        float4 wv0, wv1;
        bool more = (k0 + 16) < 512;
        if (more) {
            int kk = k0 + 16 + ap * 8, h = kk >> 6;
            float za = zs[arow][h * 2], zb = zs[arow][h * 2 + 1];
            #pragma unroll
            for (int j = 0; j < 8; j++) {
                int k = kk + j;
                av[j] = elu_f(fmaf(za, W1s[k], fmaf(zb, W1s[512 + k], b1s[k])));
            }
            wv0 = *(const float4*)(W + (size_t)(k0 + 16 + wk) * Nc + cb + wc * 4);
            wv1 = *(const float4*)(W + (size_t)(k0 + 16 + wk + 8) * Nc + cb + wc * 4);
        }
        #pragma unroll
        for (int k = 0; k < 16; k++) {
            float4 a0 = *(const float4*)&As[p][k][ty * 4];
            float4 a1 = *(const float4*)&As[p][k][64 + ty * 4];
            float4 b0 = *(const float4*)&Ws[p][k][tx * 4];
            float4 b1v = *(const float4*)&Ws[p][k][64 + tx * 4];
            float a[8] = {a0.x, a0.y, a0.z, a0.w, a1.x, a1.y, a1.z, a1.w};
            float bv[8] = {b0.x, b0.y, b0.z, b0.w, b1v.x, b1v.y, b1v.z, b1v.w};
            #pragma unroll
            for (int i = 0; i < 8; i++)
                #pragma unroll
                for (int j = 0; j < 8; j++)
                    acc[i][j] = fmaf(a[i], bv[j], acc[i][j]);
        }
        if (more) {
            int q = p ^ 1;
            #pragma unroll
            for (int j = 0; j < 8; j++) As[q][ap * 8 + j][arow] = av[j];
            *(float4*)&Ws[q][wk][wc * 4] = wv0;
            *(float4*)&Ws[q][wk + 8][wc * 4] = wv1;
        }
        __syncthreads();
    }
    #pragma unroll
    for (int i = 0; i < 8; i++) {
        int r = rb + ((i < 4) ? (ty * 4 + i) : (64 + ty * 4 + i - 4));
        *(float4*)(C + (size_t)r * Nc + cb + tx * 4) = make_float4(acc[i][0], acc[i][1], acc[i][2], acc[i][3]);
        *(float4*)(C + (size_t)r * Nc + cb + 64 + tx * 4) = make_float4(acc[i][4], acc[i][5], acc[i][6], acc[i][7]);
    }
}

// ---------------- plain 128x128 fp32 GEMM, double-buffered (layer 3) ----------------
__global__ __launch_bounds__(256, 2)
void gemm128(const float* __restrict__ A, const float* __restrict__ W,
             float* __restrict__ C, int K, int Nc) {
    __shared__ float As[2][16][136];
    __shared__ float Ws[2][16][136];
    const int tid = threadIdx.x;
    const int tx = tid & 15, ty = tid >> 4;
    const int rb = blockIdx.y * 128, cb = blockIdx.x * 128;
    const int arow = tid >> 1, ap = tid & 1;
    const int wk = tid >> 5, wc = tid & 31;
    {
        const float* abase = A + (size_t)(rb + arow) * K + ap * 8;
        float4 av0 = *(const float4*)(abase);
        float4 av1 = *(const float4*)(abase + 4);
        As[0][ap * 8 + 0][arow] = av0.x; As[0][ap * 8 + 1][arow] = av0.y;
        As[0][ap * 8 + 2][arow] = av0.z; As[0][ap * 8 + 3][arow] = av0.w;
        As[0][ap * 8 + 4][arow] = av1.x; As[0][ap * 8 + 5][arow] = av1.y;
        As[0][ap * 8 + 6][arow] = av1.z; As[0][ap * 8 + 7][arow] = av1.w;
        *(float4*)&Ws[0][wk][wc * 4]     = *(const float4*)(W + (size_t)wk * Nc + cb + wc * 4);
        *(float4*)&Ws[0][wk + 8][wc * 4] = *(const float4*)(W + (size_t)(wk + 8) * Nc + cb + wc * 4);
    }
    __syncthreads();
    float acc[8][8] = {};
    for (int k0 = 0; k0 < K; k0 += 16) {
        int p = (k0 >> 4) & 1;
        float4 av0, av1, wv0, wv1;
        bool more = (k0 + 16) < K;
        if (more) {
            const float* abase = A + (size_t)(rb + arow) * K + k0 + 16 + ap * 8;
            av0 = *(const float4*)(abase);
            av1 = *(const float4*)(abase + 4);
            wv0 = *(const float4*)(W + (size_t)(k0 + 16 + wk) * Nc + cb + wc * 4);
            wv1 = *(const float4*)(W + (size_t)(k0 + 16 + wk + 8) * Nc + cb + wc * 4);
        }
        #pragma unroll
        for (int k = 0; k < 16; k++) {
            float4 a0 = *(const float4*)&As[p][k][ty * 4];
            float4 a1 = *(const float4*)&As[p][k][64 + ty * 4];
            float4 b0 = *(const float4*)&Ws[p][k][tx * 4];
            float4 b1 = *(const float4*)&Ws[p][k][64 + tx * 4];
            float a[8] = {a0.x, a0.y, a0.z, a0.w, a1.x, a1.y, a1.z, a1.w};
            float bv[8] = {b0.x, b0.y, b0.z, b0.w, b1.x, b1.y, b1.z, b1.w};
            #pragma unroll
            for (int i = 0; i < 8; i++)
                #pragma unroll
                for (int j = 0; j < 8; j++)
                    acc[i][j] = fmaf(a[i], bv[j], acc[i][j]);
        }
        if (more) {
            int q = p ^ 1;
            As[q][ap * 8 + 0][arow] = av0.x; As[q][ap * 8 + 1][arow] = av0.y;
            As[q][ap * 8 + 2][arow] = av0.z; As[q][ap * 8 + 3][arow] = av0.w;
            As[q][ap * 8 + 4][arow] = av1.x; As[q][ap * 8 + 5][arow] = av1.y;
            As[q][ap * 8 + 6][arow] = av1.z; As[q][ap * 8 + 7][arow] = av1.w;
            *(float4*)&Ws[q][wk][wc * 4] = wv0;
            *(float4*)&Ws[q][wk + 8][wc * 4] = wv1;
        }
        __syncthreads();
    }
    #pragma unroll
    for (int i = 0; i < 8; i++) {
        int r = rb + ((i < 4) ? (ty * 4 + i) : (64 + ty * 4 + i - 4));
        *(float4*)(C + (size_t)r * Nc + cb + tx * 4) = make_float4(acc[i][0], acc[i][1], acc[i][2], acc[i][3]);
        *(float4*)(C + (size_t)r * Nc + cb + 64 + tx * 4) = make_float4(acc[i][4], acc[i][5], acc[i][6], acc[i][7]);
    }
}

// ---------------- L4 GEMM ----------------
__global__ void gemm_l4(const float* __restrict__ X, const float* __restrict__ W4,
                        float* __restrict__ Y) {
    __shared__ float w[1024];
    int tid = threadIdx.x;
    for (int i = tid; i < 1024; i += blockDim.x) w[i] = W4[i];
    __syncthreads();
    int idx = blockIdx.x * blockDim.x + tid;
    if (idx >= TN * 8) return;
    int row = idx >> 3, j = idx & 7;
    const float4* xr = (const float4*)(X + (size_t)row * 128);
    float acc = 0.f;
    #pragma unroll 8
    for (int k = 0; k < 32; k++) {
        float4 v = xr[k];
        acc = fmaf(v.x, w[(k * 4 + 0) * 8 + j], acc);
        acc = fmaf(v.y, w[(k * 4 + 1) * 8 + j], acc);
        acc = fmaf(v.z, w[(k * 4 + 2) * 8 + j], acc);
        acc = fmaf(v.w, w[(k * 4 + 3) * 8 + j], acc);
    }
    Y[idx] = acc;
}

// ---------------- fully fused GAT, node-per-thread phase 3 ----------------
template<int H, int C, bool LSRC_SMEM>
__global__ __launch_bounds__(1024, 1)
void fused_gat(const float* __restrict__ Y, const float* __restrict__ as_,
               const float* __restrict__ ad_, const float* __restrict__ bias,
               float* __restrict__ Xout) {
    extern __shared__ float sm[];
    constexpr int HC = H * C;
    constexpr int Q = C / 4;
    float* tile   = sm;                          // NPG*C
    float* es_s   = tile + NPG * C;              // NPG
    float* ed_s   = es_s + NPG;                  // NPG
    float* alphaS = ed_s + NPG;                  // NPG*17
    int*   lsrcS  = (int*)(alphaS + NPG * 17);   // NPG*16 (optional)
    __shared__ float as_s[C], ad_s[C], bi_s[C];
    int blk = blockIdx.x;
    int h = (H == 1) ? 0 : (blk % H);
    int tb = (H == 1) ? blk : (blk / H);
    int b = tb % B_GR;
    int t = tb / B_GR;
    int base = t * N_NODES + b * NPG;
    int tid = threadIdx.x;
    const int* lg = g_lsrc + (size_t)b * NPG * 16;
    if (tid < C) { as_s[tid] = as_[h * C + tid]; ad_s[tid] = ad_[h * C + tid]; bi_s[tid] = bias[h * C + tid]; }
    for (int i = tid; i < NPG * Q; i += blockDim.x) {
        int n = i / Q, q = i % Q;
        *(float4*)&tile[n * C + q * 4] =
            *(const float4*)(Y + (size_t)(base + n) * HC + h * C + q * 4);
    }
    if (LSRC_SMEM) {
        for (int i = tid; i < NPG * 4; i += blockDim.x)
            ((int4*)lsrcS)[i] = ((const int4*)lg)[i];
    }
    __syncthreads();
    // phase 1: es/ed per node (lane-rotated)
    for (int n = tid; n < NPG; n += blockDim.x) {
        const float* tn = tile + n * C;
        int rot1 = tid & (Q - 1);
        float se = 0.f, de = 0.f;
        #pragma unroll
        for (int jj = 0; jj < Q; jj++) {
            int q = (jj + rot1) & (Q - 1);
            float4 v = *(const float4*)&tn[q * 4];
            float4 a = *(const float4*)&as_s[q * 4];
            float4 d = *(const float4*)&ad_s[q * 4];
            se = fmaf(v.x, a.x, fmaf(v.y, a.y, fmaf(v.z, a.z, fmaf(v.w, a.w, se))));
            de = fmaf(v.x, d.x, fmaf(v.y, d.y, fmaf(v.z, d.z, fmaf(v.w, d.w, de))));
        }
        es_s[n] = se; ed_s[n] = de;
    }
    __syncthreads();
    // phase 2: softmax -> alphaS
    for (int n = tid; n < NPG; n += blockDim.x) {
        const int4* ls4 = LSRC_SMEM ? (const int4*)(lsrcS + n * 16)
                                    : (const int4*)(lg + n * 16);
        int4 iA = ls4[0], iB = ls4[1], iC_ = ls4[2], iD = ls4[3];
        int idxs[16] = {iA.x, iA.y, iA.z, iA.w, iB.x, iB.y, iB.z, iB.w,
                        iC_.x, iC_.y, iC_.z, iC_.w, iD.x, iD.y, iD.z, iD.w};
        float ed = ed_s[n];
        float m = lrelu(es_s[n] + ed);
        #pragma unroll
        for (int k = 0; k < 16; k++) m = fmaxf(m, lrelu(es_s[idxs[k]] + ed));
        float* ap = alphaS + n * 17;
        float ssum = 0.f;
        #pragma unroll
        for (int k = 0; k < 16; k++) {
            float v = exp_neg(lrelu(es_s[idxs[k]] + ed) - m);
            ap[k] = v; ssum += v;
        }
        { float v = exp_neg(lrelu(es_s[n] + ed) - m); ap[16] = v; ssum += v; }
        float inv = 1.f / (ssum + 1e-16f);
        #pragma unroll
        for (int k = 0; k < 17; k++) ap[k] *= inv;
    }
    __syncthreads();
    // phase 3: node-per-thread aggregation, rotated q, register accumulators
    {
        int rot = tid & (Q - 1);
        int qb[Q];
        #pragma unroll
        for (int jj = 0; jj < Q; jj++) qb[jj] = ((jj + rot) & (Q - 1)) * 4;
        for (int n = tid; n < NPG; n += blockDim.x) {
            const float* ap = alphaS + n * 17;
            const int* ls = LSRC_SMEM ? (lsrcS + n * 16) : (lg + n * 16);
            float4 acc[Q];
            {
                float a = ap[16];
                const float* tn = tile + n * C;
                #pragma unroll
                for (int jj = 0; jj < Q; jj++) {
                    float4 v = *(const float4*)&tn[qb[jj]];
                    acc[jj].x = a * v.x; acc[jj].y = a * v.y;
                    acc[jj].z = a * v.z; acc[jj].w = a * v.w;
                }
            }
            #pragma unroll 4
            for (int k = 0; k < 16; k++) {
                int idx = ls[k];
                float a = ap[k];
                const float* tr = tile + idx * C;
                #pragma unroll
                for (int jj = 0; jj < Q; jj++) {
                    float4 v = *(const float4*)&tr[qb[jj]];
                    acc[jj].x = fmaf(a, v.x, acc[jj].x); acc[jj].y = fmaf(a, v.y, acc[jj].y);
                    acc[jj].z = fmaf(a, v.z, acc[jj].z); acc[jj].w = fmaf(a, v.w, acc[jj].w);
                }
            }
            float* orow = Xout + (size_t)(base + n) * HC + h * C;
            #pragma unroll
            for (int jj = 0; jj < Q; jj++) {
                int qo = qb[jj];
                float4 o;
                o.x = elu_f(acc[jj].x + bi_s[qo + 0]);
                o.y = elu_f(acc[jj].y + bi_s[qo + 1]);
                o.z = elu_f(acc[jj].z + bi_s[qo + 2]);
                o.w = elu_f(acc[jj].w + bi_s[qo + 3]);
                *(float4*)&orow[qo] = o;
            }
        }
    }
}

// ---------------- mean pool ----------------
__global__ void pool_kernel(const float* __restrict__ X4) {
    int tb = blockIdx.x;
    int t = tb / B_GR, b = tb % B_GR;
    int tid = threadIdx.x;
    float acc[8] = {};
    for (int nn = tid; nn < NPG; nn += blockDim.x) {
        const float* p = X4 + ((size_t)(t * N_NODES + b * NPG + nn)) * 8;
        #pragma unroll
        for (int f = 0; f < 8; f++) acc[f] += p[f];
    }
    __shared__ float s[8];
    if (tid < 8) s[tid] = 0.f;
    __syncthreads();
    #pragma unroll
    for (int f = 0; f < 8; f++) atomicAdd(&s[f], acc[f]);
    __syncthreads();
    if (tid < 8) g_emb[tb * 8 + tid] = s[tid] * (1.0f / (float)NPG);
}

// ---------------- LSTM + FC ----------------
__device__ __forceinline__ float sigmoidf(float x) { return 1.f / (1.f + expf(-x)); }

__global__ void lstm_fc(const float* __restrict__ w_ih, const float* __restrict__ w_hh,
                        const float* __restrict__ b_ih, const float* __restrict__ b_hh,
                        const float* __restrict__ w_fc, const float* __restrict__ b_fc,
                        float* __restrict__ out) {
    __shared__ float h[8][128], c[8][128], g[8][512], xs[8][8];
    int tid = threadIdx.x;
    for (int i = tid; i < 8 * 128; i += 1024) { ((float*)h)[i] = 0.f; ((float*)c)[i] = 0.f; }
    __syncthreads();
    for (int t = 0; t < T_STEPS; t++) {
        if (tid < 64) xs[tid >> 3][tid & 7] = g_emb[t * 64 + tid];
        __syncthreads();
        #pragma unroll
        for (int task = tid; task < 4096; task += 1024) {
            int b = task >> 9, row = task & 511;
            float acc = b_ih[row] + b_hh[row];
            const float* wi = w_ih + row * 8;
            #pragma unroll
            for (int k = 0; k < 8; k++) acc += xs[b][k] * wi[k];
            const float4* wh = (const float4*)(w_hh + row * 128);
            const float4* hb = (const float4*)h[b];
            #pragma unroll 8
            for (int j = 0; j < 32; j++) {
                float4 w4 = wh[j], h4 = hb[j];
                acc = fmaf(w4.x, h4.x, acc); acc = fmaf(w4.y, h4.y, acc);
                acc = fmaf(w4.z, h4.z, acc); acc = fmaf(w4.w, h4.w, acc);
            }
            g[b][row] = acc;
        }
        __syncthreads();
        if (tid < 1024) {
            int b = tid >> 7, u = tid & 127;
            float ig = sigmoidf(g[b][u]);
            float fg = sigmoidf(g[b][128 + u]);
            float gg = tanhf(g[b][256 + u]);
            float og = sigmoidf(g[b][384 + u]);
            float cn = fg * c[b][u] + ig * gg;
            c[b][u] = cn;
            h[b][u] = og * tanhf(cn);
        }
        __syncthreads();
    }
    if (tid < 16) {
        int b = tid >> 1, o = tid & 1;
        float acc = b_fc[o];
        const float* w = w_fc + o * 128;
        #pragma unroll 8
        for (int j = 0; j < 128; j++) acc += h[b][j] * w[j];
        out[b * 2 + o] = acc;
    }
}

// ---------------- host launch ----------------
extern "C" void kernel_launch(void* const* d_in, const int* in_sizes, int n_in,
                              void* d_out, int out_size) {
    const float *x_seq = 0, *W1 = 0, *as1 = 0, *ad1 = 0, *b1 = 0;
    const float *W2 = 0, *as2 = 0, *ad2 = 0, *b2 = 0;
    const float *W3 = 0, *as3 = 0, *ad3 = 0, *b3 = 0;
    const float *W4 = 0, *as4 = 0, *ad4 = 0, *b4 = 0;
    const float *w_ih = 0, *w_hh = 0, *b_ih = 0, *b_hh = 0, *w_fc = 0, *b_fc = 0;
    const int *edge = 0;
    int c1024 = 0, c512 = 0, c256 = 0, c128 = 0, c8 = 0;
    for (int i = 0; i < n_in; i++) {
        const float* p = (const float*)d_in[i];
        switch (in_sizes[i]) {
            case 172800: x_seq = p; break;
            case 276480: edge = (const int*)p; break;
            case 8640:   break;
            case 131072: W2 = p; break;
            case 65536:  w_hh = p; break;
            case 32768:  W3 = p; break;
            case 4096:   w_ih = p; break;
            case 1024:   { if (c1024++ == 0) W1 = p; else W4 = p; } break;
            case 512: { int k = c512++;
                if (k == 0) as1 = p; else if (k == 1) ad1 = p; else if (k == 2) b1 = p;
                else if (k == 3) b_ih = p; else b_hh = p; } break;
            case 256: { int k = c256++;
                if (k == 0) as2 = p; else if (k == 1) ad2 = p; else if (k == 2) b2 = p;
                else w_fc = p; } break;
            case 128: { int k = c128++;
                if (k == 0) as3 = p; else if (k == 1) ad3 = p; else b3 = p; } break;
            case 8: { int k = c8++;
                if (k == 0) as4 = p; else if (k == 1) ad4 = p; else b4 = p; } break;
            case 2: b_fc = p; break;
            default: break;
        }
    }
    const int* src = edge;

    float *bufA, *bufB;
    cudaGetSymbolAddress((void**)&bufA, g_bufA);
    cudaGetSymbolAddress((void**)&bufB, g_bufB);

    const int SM_L1   = (NPG * 2 + NPG * 8 * 2) * 4;                       // 77760
    const int SM_F32  = (NPG * 32 + NPG * 2 + NPG * 17) * 4;               // 220320 (no lsrc)
    const int SM_F16  = (NPG * 16 + NPG * 2 + NPG * 17 + NPG * 16) * 4;    // 220320
    const int SM_F8   = (NPG * 8  + NPG * 2 + NPG * 17 + NPG * 16) * 4;    // 185760
    cudaFuncSetAttribute(l1_fused, cudaFuncAttributeMaxDynamicSharedMemorySize, SM_L1);
    cudaFuncSetAttribute(fused_gat<8, 32, false>, cudaFuncAttributeMaxDynamicSharedMemorySize, SM_F32);
    cudaFuncSetAttribute(fused_gat<8, 16, true>,  cudaFuncAttributeMaxDynamicSharedMemorySize, SM_F16);
    cudaFuncSetAttribute(fused_gat<1, 8, true>,   cudaFuncAttributeMaxDynamicSharedMemorySize, SM_F8);

    // launch 1: setup
    setup_kernel<<<541, 256>>>(src, W1, as1, ad1);
    // launch 2: layer-1 fused softmax/aggregate
    l1_fused<<<T_STEPS * B_GR, 1024, SM_L1>>>(x_seq);
    // launch 3: L2 GEMM (fused L1 expansion)
    l1gemm<<<dim3(2, TN / 128), 256>>>(W1, b1, W2, bufA, 256);
    // launch 4 (PROFILED): big gather
    fused_gat<8, 32, false><<<T_STEPS * B_GR * 8, 1024, SM_F32>>>(bufA, as2, ad2, b2, bufB);

    gemm128<<<dim3(1, TN / 128), 256>>>(bufB, W3, bufA, 256, 128);
    fused_gat<8, 16, true><<<T_STEPS * B_GR * 8, 1024, SM_F16>>>(bufA, as3, ad3, b3, bufB);

    gemm_l4<<<(TN * 8 + 255) / 256, 256>>>(bufB, W4, bufA);
    fused_gat<1, 8, true><<<T_STEPS * B_GR, 1024, SM_F8>>>(bufA, as4, ad4, b4, bufB);

    pool_kernel<<<T_STEPS * B_GR, 256>>>(bufB);
    lstm_fc<<<1, 1024>>>(w_ih, w_hh, b_ih, b_hh, w_fc, b_fc, (float*)d_out);
}

// round 7
// speedup vs baseline: 1.1478x; 1.1478x over previous
#include <cuda_runtime.h>
#include <cuda_bf16.h>
#include <math.h>

#define T_STEPS 10
#define B_GR    8
#define NPG     1080
#define N_NODES 8640
#define TN      86400
#define DEG     16

// ---------------- scratch ----------------
__device__ float g_bufA[(size_t)TN * 256];
__device__ float g_bufB[(size_t)TN * 128];
__device__ __nv_bfloat16 g_X1hi[(size_t)TN * 512];
__device__ __nv_bfloat16 g_X1lo[(size_t)TN * 512];
__device__ __nv_bfloat16 g_Xhi[(size_t)TN * 256];
__device__ __nv_bfloat16 g_Xlo[(size_t)TN * 256];
__device__ __nv_bfloat16 g_W2hi[512 * 256], g_W2lo[512 * 256];
__device__ __nv_bfloat16 g_W3hi[256 * 128], g_W3lo[256 * 128];
__device__ float g_emb[T_STEPS * B_GR * 8];
__device__ float g_uv[32];
__device__ int   g_lsrc[N_NODES * 16];

struct alignas(16) B16x8 { __nv_bfloat16 v[8]; };
struct alignas(8)  B16x4 { __nv_bfloat16 v[4]; };

__device__ __forceinline__ void split_bf16(float x, __nv_bfloat16& h, __nv_bfloat16& l) {
    h = __float2bfloat16_rn(x);
    l = __float2bfloat16_rn(x - __bfloat162float(h));
}

// ---------------- fast exp for x <= 0 ----------------
__device__ __forceinline__ float exp_neg(float x) {
    x = fmaxf(x, -87.0f);
    const float L2E = 1.4426950408889634f;
    float z = fmaf(x, L2E, 12582912.0f);
    int   ei = __float_as_int(z);
    float n = z - 12582912.0f;
    float f = fmaf(x, L2E, -n);
    float r = fmaf(1.5403530e-4f, f, 1.3333558e-3f);
    r = fmaf(r, f, 9.6181291e-3f);
    r = fmaf(r, f, 5.5504109e-2f);
    r = fmaf(r, f, 2.4022651e-1f);
    r = fmaf(r, f, 6.9314718e-1f);
    r = fmaf(r, f, 1.0f);
    float s = __int_as_float((ei + 127) << 23);
    return r * s;
}
__device__ __forceinline__ float elu_f(float v) { return v > 0.f ? v : exp_neg(v) - 1.f; }
__device__ __forceinline__ float lrelu(float e) { return e >= 0.f ? e : 0.2f * e; }

// ---------------- setup kernels ----------------
__global__ void prep_lsrc(const int* __restrict__ src) {
    int i = blockIdx.x * 256 + threadIdx.x;      // 540*256 == N_NODES*16
    int b = i / (NPG * 16);
    g_lsrc[i] = src[i] - b * NPG;
}

__global__ void setup2(const float* __restrict__ W2, const float* __restrict__ W3,
                       const float* __restrict__ W1, const float* __restrict__ as1,
                       const float* __restrict__ ad1) {
    int bid = blockIdx.x, tid = threadIdx.x;
    if (bid < 512) {
        int i = bid * 256 + tid;                  // 512*256 == 131072
        split_bf16(W2[i], g_W2hi[i], g_W2lo[i]);
    } else if (bid < 640) {
        int i = (bid - 512) * 256 + tid;          // 128*256 == 32768
        split_bf16(W3[i], g_W3hi[i], g_W3lo[i]);
    } else if (tid < 32) {
        int d = tid >> 4, h = (tid >> 1) & 7, f = tid & 1;
        const float* a = d ? ad1 : as1;
        float s = 0.f;
        #pragma unroll
        for (int c = 0; c < 64; c++) s += W1[f * 512 + h * 64 + c] * a[h * 64 + c];
        g_uv[tid] = s;
    }
}

// ---------------- layer 1 fully fused: x -> X1 (split bf16) ----------------
__global__ __launch_bounds__(1024, 1)
void l1_fused(const float* __restrict__ x, const float* __restrict__ W1,
              const float* __restrict__ b1) {
    extern __shared__ float sm[];
    float* xs   = sm;                   // NPG*2
    float* es_s = xs + NPG * 2;         // NPG*8
    float* ed_s = es_s + NPG * 8;       // NPG*8
    float* zS   = ed_s + NPG * 8;       // NPG*16
    float* W1s  = zS + NPG * 16;        // 1024
    float* b1s  = W1s + 1024;           // 512
    __shared__ float uvS[32];
    int tb = blockIdx.x;
    int b = tb & 7, t = tb >> 3;
    int base = t * N_NODES + b * NPG;
    int tid = threadIdx.x;
    if (tid < 32) uvS[tid] = g_uv[tid];
    for (int i = tid; i < 1024; i += 1024) W1s[i] = W1[i];
    if (tid < 512) b1s[tid] = b1[tid];
    for (int i = tid; i < NPG * 2; i += 1024) xs[i] = x[(size_t)base * 2 + i];
    __syncthreads();
    for (int task = tid; task < NPG * 8; task += 1024) {
        int n = task >> 3, h = task & 7;
        float x0 = xs[n * 2], x1 = xs[n * 2 + 1];
        es_s[task] = fmaf(x0, uvS[h * 2], x1 * uvS[h * 2 + 1]);
        ed_s[task] = fmaf(x0, uvS[16 + h * 2], x1 * uvS[16 + h * 2 + 1]);
    }
    __syncthreads();
    for (int task = tid; task < NPG * 8; task += 1024) {
        int n = task >> 3, h = task & 7;
        const int4* ls4 = (const int4*)(g_lsrc + ((size_t)b * NPG + n) * 16);
        int4 iA = ls4[0], iB = ls4[1], iC = ls4[2], iD = ls4[3];
        int idxs[16] = {iA.x, iA.y, iA.z, iA.w, iB.x, iB.y, iB.z, iB.w,
                        iC.x, iC.y, iC.z, iC.w, iD.x, iD.y, iD.z, iD.w};
        float ed = ed_s[task];
        float ev[17];
        float m = -1e30f;
        #pragma unroll
        for (int k = 0; k < 16; k++) {
            float e = lrelu(es_s[idxs[k] * 8 + h] + ed);
            ev[k] = e; m = fmaxf(m, e);
        }
        { float e = lrelu(es_s[task] + ed); ev[16] = e; m = fmaxf(m, e); }
        float ssum = 0.f;
        #pragma unroll
        for (int k = 0; k < 17; k++) { float v = exp_neg(ev[k] - m); ev[k] = v; ssum += v; }
        float inv = 1.f / (ssum + 1e-16f);
        float z0 = 0.f, z1 = 0.f;
        #pragma unroll
        for (int k = 0; k < 16; k++) {
            float a = ev[k] * inv;
            z0 = fmaf(a, xs[idxs[k] * 2], z0);
            z1 = fmaf(a, xs[idxs[k] * 2 + 1], z1);
        }
        {
            float a = ev[16] * inv;
            z0 = fmaf(a, xs[n * 2], z0);
            z1 = fmaf(a, xs[n * 2 + 1], z1);
        }
        zS[n * 16 + h * 2] = z0;
        zS[n * 16 + h * 2 + 1] = z1;
    }
    __syncthreads();
    // expansion: X1[base+n][k] = elu(z0*W1[k] + z1*W1[512+k] + b1[k]), split bf16
    for (int i = tid; i < NPG * 64; i += 1024) {
        int n = i >> 6, kg = i & 63;
        int k0 = kg * 8, h = kg >> 3;
        float z0 = zS[n * 16 + h * 2], z1 = zS[n * 16 + h * 2 + 1];
        B16x8 hv, lv;
        #pragma unroll
        for (int j = 0; j < 8; j++) {
            int k = k0 + j;
            float v = elu_f(fmaf(z0, W1s[k], fmaf(z1, W1s[512 + k], b1s[k])));
            split_bf16(v, hv.v[j], lv.v[j]);
        }
        size_t off = (size_t)(base + n) * 512 + k0;
        *(B16x8*)(g_X1hi + off) = hv;
        *(B16x8*)(g_X1lo + off) = lv;
    }
}

// ---------------- bf16x3 tensor-core GEMM: C[M,Nc] = A@W (fp32-equivalent) ----------------
// block tile 128x128, 8 warps (4Mx2N), warp tile 32x64, mma.sync m16n8k16
#define MMA_BF16(d, a0, a1, a2, a3, b0, b1) \
    asm volatile("mma.sync.aligned.m16n8k16.row.col.f32.bf16.bf16.f32 " \
        "{%0,%1,%2,%3}, {%4,%5,%6,%7}, {%8,%9}, {%0,%1,%2,%3};" \
        : "+f"(d[0]), "+f"(d[1]), "+f"(d[2]), "+f"(d[3]) \
        : "r"(a0), "r"(a1), "r"(a2), "r"(a3), "r"(b0), "r"(b1))

#define BSTR 18   // padded B row stride (shorts)

__global__ __launch_bounds__(256)
void gemm_bf16(const __nv_bfloat16* __restrict__ Ahi, const __nv_bfloat16* __restrict__ Alo,
               const __nv_bfloat16* __restrict__ Whi, const __nv_bfloat16* __restrict__ Wlo,
               float* __restrict__ C, int K, int Nc) {
    __shared__ alignas(16) unsigned short sA[2][2][128 * 16];
    __shared__ alignas(16) unsigned short sB[2][2][128 * BSTR];
    const int tid = threadIdx.x;
    const int lane = tid & 31, wid = tid >> 5;
    const int warpM = wid & 3, warpN = wid >> 2;
    const int rb = blockIdx.y * 128, cb = blockIdx.x * 128;
    const int arow = tid >> 1, aseg = tid & 1;
    const int bk = tid >> 4, bn0 = (tid & 15) * 8;
    float acc[2][8][4] = {};
    // prologue: stage chunk 0 -> buf 0
    {
        uint4 vah = *(const uint4*)(Ahi + (size_t)(rb + arow) * K + aseg * 8);
        uint4 val = *(const uint4*)(Alo + (size_t)(rb + arow) * K + aseg * 8);
        *(uint4*)&sA[0][0][arow * 16 + aseg * 8] = vah;
        *(uint4*)&sA[0][1][arow * 16 + aseg * 8] = val;
        uint4 vbh = *(const uint4*)(Whi + (size_t)bk * Nc + cb + bn0);
        uint4 vbl = *(const uint4*)(Wlo + (size_t)bk * Nc + cb + bn0);
        const unsigned short* ph = (const unsigned short*)&vbh;
        const unsigned short* pl = (const unsigned short*)&vbl;
        #pragma unroll
        for (int j = 0; j < 8; j++) {
            sB[0][0][(bn0 + j) * BSTR + bk] = ph[j];
            sB[0][1][(bn0 + j) * BSTR + bk] = pl[j];
        }
    }
    __syncthreads();
    const int nk = K >> 4;
    for (int ck = 0; ck < nk; ck++) {
        int p = ck & 1;
        uint4 vah, val, vbh, vbl;
        bool more = (ck + 1) < nk;
        if (more) {
            int k0 = (ck + 1) << 4;
            vah = *(const uint4*)(Ahi + (size_t)(rb + arow) * K + k0 + aseg * 8);
            val = *(const uint4*)(Alo + (size_t)(rb + arow) * K + k0 + aseg * 8);
            vbh = *(const uint4*)(Whi + (size_t)(k0 + bk) * Nc + cb + bn0);
            vbl = *(const uint4*)(Wlo + (size_t)(k0 + bk) * Nc + cb + bn0);
        }
        const unsigned short* Ah = sA[p][0];
        const unsigned short* Al = sA[p][1];
        const unsigned short* Bh = sB[p][0];
        const unsigned short* Bl = sB[p][1];
        unsigned ah[2][4], al[2][4];
        #pragma unroll
        for (int ma = 0; ma < 2; ma++) {
            int r = warpM * 32 + ma * 16 + (lane >> 2);
            int c0 = (lane & 3) * 2;
            ah[ma][0] = *(const unsigned*)(Ah + r * 16 + c0);
            ah[ma][1] = *(const unsigned*)(Ah + (r + 8) * 16 + c0);
            ah[ma][2] = *(const unsigned*)(Ah + r * 16 + c0 + 8);
            ah[ma][3] = *(const unsigned*)(Ah + (r + 8) * 16 + c0 + 8);
            al[ma][0] = *(const unsigned*)(Al + r * 16 + c0);
            al[ma][1] = *(const unsigned*)(Al + (r + 8) * 16 + c0);
            al[ma][2] = *(const unsigned*)(Al + r * 16 + c0 + 8);
            al[ma][3] = *(const unsigned*)(Al + (r + 8) * 16 + c0 + 8);
        }
        #pragma unroll
        for (int na = 0; na < 8; na++) {
            int n = warpN * 64 + na * 8 + (lane >> 2);
            int k2 = (lane & 3) * 2;
            unsigned bh0 = *(const unsigned*)(Bh + n * BSTR + k2);
            unsigned bh1 = *(const unsigned*)(Bh + n * BSTR + k2 + 8);
            unsigned bl0 = *(const unsigned*)(Bl + n * BSTR + k2);
            unsigned bl1 = *(const unsigned*)(Bl + n * BSTR + k2 + 8);
            #pragma unroll
            for (int ma = 0; ma < 2; ma++) {
                MMA_BF16(acc[ma][na], ah[ma][0], ah[ma][1], ah[ma][2], ah[ma][3], bh0, bh1);
                MMA_BF16(acc[ma][na], ah[ma][0], ah[ma][1], ah[ma][2], ah[ma][3], bl0, bl1);
                MMA_BF16(acc[ma][na], al[ma][0], al[ma][1], al[ma][2], al[ma][3], bh0, bh1);
            }
        }
        __syncthreads();
        if (more) {
            int q = p ^ 1;
            *(uint4*)&sA[q][0][arow * 16 + aseg * 8] = vah;
            *(uint4*)&sA[q][1][arow * 16 + aseg * 8] = val;
            const unsigned short* ph = (const unsigned short*)&vbh;
            const unsigned short* pl = (const unsigned short*)&vbl;
            #pragma unroll
            for (int j = 0; j < 8; j++) {
                sB[q][0][(bn0 + j) * BSTR + bk] = ph[j];
                sB[q][1][(bn0 + j) * BSTR + bk] = pl[j];
            }
            __syncthreads();
        }
    }
    #pragma unroll
    for (int ma = 0; ma < 2; ma++) {
        #pragma unroll
        for (int na = 0; na < 8; na++) {
            int r0 = rb + warpM * 32 + ma * 16 + (lane >> 2);
            int c = cb + warpN * 64 + na * 8 + (lane & 3) * 2;
            *(float2*)(C + (size_t)r0 * Nc + c)       = make_float2(acc[ma][na][0], acc[ma][na][1]);
            *(float2*)(C + (size_t)(r0 + 8) * Nc + c) = make_float2(acc[ma][na][2], acc[ma][na][3]);
        }
    }
}

// ---------------- L4 GEMM (fp32, tiny) ----------------
__global__ void gemm_l4(const float* __restrict__ X, const float* __restrict__ W4,
                        float* __restrict__ Y) {
    __shared__ float w[1024];
    int tid = threadIdx.x;
    for (int i = tid; i < 1024; i += blockDim.x) w[i] = W4[i];
    __syncthreads();
    int idx = blockIdx.x * blockDim.x + tid;
    if (idx >= TN * 8) return;
    int row = idx >> 3, j = idx & 7;
    const float4* xr = (const float4*)(X + (size_t)row * 128);
    float acc = 0.f;
    #pragma unroll 8
    for (int k = 0; k < 32; k++) {
        float4 v = xr[k];
        acc = fmaf(v.x, w[(k * 4 + 0) * 8 + j], acc);
        acc = fmaf(v.y, w[(k * 4 + 1) * 8 + j], acc);
        acc = fmaf(v.z, w[(k * 4 + 2) * 8 + j], acc);
        acc = fmaf(v.w, w[(k * 4 + 3) * 8 + j], acc);
    }
    Y[idx] = acc;
}

// ---------------- fully fused GAT (R5 task-per-thread phase 3) ----------------
template<int H, int C, bool LSRC_SMEM, bool OUT_SPLIT>
__global__ __launch_bounds__(1024, 1)
void fused_gat(const float* __restrict__ Y, const float* __restrict__ as_,
               const float* __restrict__ ad_, const float* __restrict__ bias,
               float* __restrict__ Xout) {
    extern __shared__ float sm[];
    constexpr int HC = H * C;
    constexpr int Q = C / 4;
    float* tile   = sm;
    float* es_s   = tile + NPG * C;
    float* ed_s   = es_s + NPG;
    float* alphaS = ed_s + NPG;
    int*   lsrcS  = (int*)(alphaS + NPG * 17);
    __shared__ float as_s[C], ad_s[C], bi_s[C];
    int blk = blockIdx.x;
    int h = (H == 1) ? 0 : (blk % H);
    int tb = (H == 1) ? blk : (blk / H);
    int b = tb % B_GR;
    int t = tb / B_GR;
    int base = t * N_NODES + b * NPG;
    int tid = threadIdx.x;
    const int* lg = g_lsrc + (size_t)b * NPG * 16;
    if (tid < C) { as_s[tid] = as_[h * C + tid]; ad_s[tid] = ad_[h * C + tid]; bi_s[tid] = bias[h * C + tid]; }
    for (int i = tid; i < NPG * Q; i += blockDim.x) {
        int n = i / Q, q = i % Q;
        *(float4*)&tile[n * C + q * 4] =
            *(const float4*)(Y + (size_t)(base + n) * HC + h * C + q * 4);
    }
    if (LSRC_SMEM) {
        for (int i = tid; i < NPG * 4; i += blockDim.x)
            ((int4*)lsrcS)[i] = ((const int4*)lg)[i];
    }
    __syncthreads();
    // phase 1: es/ed
    for (int n = tid; n < NPG; n += blockDim.x) {
        const float* tn = tile + n * C;
        int rot1 = tid & (Q - 1);
        float se = 0.f, de = 0.f;
        #pragma unroll
        for (int jj = 0; jj < Q; jj++) {
            int q = (jj + rot1) & (Q - 1);
            float4 v = *(const float4*)&tn[q * 4];
            float4 a = *(const float4*)&as_s[q * 4];
            float4 d = *(const float4*)&ad_s[q * 4];
            se = fmaf(v.x, a.x, fmaf(v.y, a.y, fmaf(v.z, a.z, fmaf(v.w, a.w, se))));
            de = fmaf(v.x, d.x, fmaf(v.y, d.y, fmaf(v.z, d.z, fmaf(v.w, d.w, de))));
        }
        es_s[n] = se; ed_s[n] = de;
    }
    __syncthreads();
    // phase 2: softmax -> alphaS
    for (int n = tid; n < NPG; n += blockDim.x) {
        const int4* ls4 = LSRC_SMEM ? (const int4*)(lsrcS + n * 16)
                                    : (const int4*)(lg + n * 16);
        int4 iA = ls4[0], iB = ls4[1], iC_ = ls4[2], iD = ls4[3];
        int idxs[16] = {iA.x, iA.y, iA.z, iA.w, iB.x, iB.y, iB.z, iB.w,
                        iC_.x, iC_.y, iC_.z, iC_.w, iD.x, iD.y, iD.z, iD.w};
        float ed = ed_s[n];
        float m = lrelu(es_s[n] + ed);
        #pragma unroll
        for (int k = 0; k < 16; k++) m = fmaxf(m, lrelu(es_s[idxs[k]] + ed));
        float* ap = alphaS + n * 17;
        float ssum = 0.f;
        #pragma unroll
        for (int k = 0; k < 16; k++) {
            float v = exp_neg(lrelu(es_s[idxs[k]] + ed) - m);
            ap[k] = v; ssum += v;
        }
        { float v = exp_neg(lrelu(es_s[n] + ed) - m); ap[16] = v; ssum += v; }
        float inv = 1.f / (ssum + 1e-16f);
        #pragma unroll
        for (int k = 0; k < 17; k++) ap[k] *= inv;
    }
    __syncthreads();
    // phase 3: task-per-thread aggregation
    for (int task = tid; task < NPG * Q; task += blockDim.x) {
        int n = task / Q, q = task % Q;
        const float* ap = alphaS + n * 17;
        const int* ls = LSRC_SMEM ? (lsrcS + n * 16) : (lg + n * 16);
        float4 acc = make_float4(0.f, 0.f, 0.f, 0.f);
        #pragma unroll
        for (int k = 0; k < 16; k++) {
            int idx = ls[k];
            float a = ap[k];
            float4 v = *(const float4*)&tile[idx * C + q * 4];
            acc.x = fmaf(a, v.x, acc.x); acc.y = fmaf(a, v.y, acc.y);
            acc.z = fmaf(a, v.z, acc.z); acc.w = fmaf(a, v.w, acc.w);
        }
        {
            float a = ap[16];
            float4 v = *(const float4*)&tile[n * C + q * 4];
            acc.x = fmaf(a, v.x, acc.x); acc.y = fmaf(a, v.y, acc.y);
            acc.z = fmaf(a, v.z, acc.z); acc.w = fmaf(a, v.w, acc.w);
        }
        float o0 = elu_f(acc.x + bi_s[q * 4 + 0]);
        float o1 = elu_f(acc.y + bi_s[q * 4 + 1]);
        float o2 = elu_f(acc.z + bi_s[q * 4 + 2]);
        float o3 = elu_f(acc.w + bi_s[q * 4 + 3]);
        size_t off = (size_t)(base + n) * HC + h * C + q * 4;
        if (OUT_SPLIT) {
            B16x4 hv, lv;
            split_bf16(o0, hv.v[0], lv.v[0]);
            split_bf16(o1, hv.v[1], lv.v[1]);
            split_bf16(o2, hv.v[2], lv.v[2]);
            split_bf16(o3, hv.v[3], lv.v[3]);
            *(B16x4*)(g_Xhi + off) = hv;
            *(B16x4*)(g_Xlo + off) = lv;
        } else {
            *(float4*)(Xout + off) = make_float4(o0, o1, o2, o3);
        }
    }
}

// ---------------- mean pool ----------------
__global__ void pool_kernel(const float* __restrict__ X4) {
    int tb = blockIdx.x;
    int t = tb / B_GR, b = tb % B_GR;
    int tid = threadIdx.x;
    float acc[8] = {};
    for (int nn = tid; nn < NPG; nn += blockDim.x) {
        const float* p = X4 + ((size_t)(t * N_NODES + b * NPG + nn)) * 8;
        #pragma unroll
        for (int f = 0; f < 8; f++) acc[f] += p[f];
    }
    __shared__ float s[8];
    if (tid < 8) s[tid] = 0.f;
    __syncthreads();
    #pragma unroll
    for (int f = 0; f < 8; f++) atomicAdd(&s[f], acc[f]);
    __syncthreads();
    if (tid < 8) g_emb[tb * 8 + tid] = s[tid] * (1.0f / (float)NPG);
}

// ---------------- LSTM + FC ----------------
__device__ __forceinline__ float sigmoidf(float x) { return 1.f / (1.f + expf(-x)); }

__global__ void lstm_fc(const float* __restrict__ w_ih, const float* __restrict__ w_hh,
                        const float* __restrict__ b_ih, const float* __restrict__ b_hh,
                        const float* __restrict__ w_fc, const float* __restrict__ b_fc,
                        float* __restrict__ out) {
    __shared__ float h[8][128], c[8][128], g[8][512], xs[8][8];
    int tid = threadIdx.x;
    for (int i = tid; i < 8 * 128; i += 1024) { ((float*)h)[i] = 0.f; ((float*)c)[i] = 0.f; }
    __syncthreads();
    for (int t = 0; t < T_STEPS; t++) {
        if (tid < 64) xs[tid >> 3][tid & 7] = g_emb[t * 64 + tid];
        __syncthreads();
        #pragma unroll
        for (int task = tid; task < 4096; task += 1024) {
            int b = task >> 9, row = task & 511;
            float acc = b_ih[row] + b_hh[row];
            const float* wi = w_ih + row * 8;
            #pragma unroll
            for (int k = 0; k < 8; k++) acc += xs[b][k] * wi[k];
            const float4* wh = (const float4*)(w_hh + row * 128);
            const float4* hb = (const float4*)h[b];
            #pragma unroll 8
            for (int j = 0; j < 32; j++) {
                float4 w4 = wh[j], h4 = hb[j];
                acc = fmaf(w4.x, h4.x, acc); acc = fmaf(w4.y, h4.y, acc);
                acc = fmaf(w4.z, h4.z, acc); acc = fmaf(w4.w, h4.w, acc);
            }
            g[b][row] = acc;
        }
        __syncthreads();
        if (tid < 1024) {
            int b = tid >> 7, u = tid & 127;
            float ig = sigmoidf(g[b][u]);
            float fg = sigmoidf(g[b][128 + u]);
            float gg = tanhf(g[b][256 + u]);
            float og = sigmoidf(g[b][384 + u]);
            float cn = fg * c[b][u] + ig * gg;
            c[b][u] = cn;
            h[b][u] = og * tanhf(cn);
        }
        __syncthreads();
    }
    if (tid < 16) {
        int b = tid >> 1, o = tid & 1;
        float acc = b_fc[o];
        const float* w = w_fc + o * 128;
        #pragma unroll 8
        for (int j = 0; j < 128; j++) acc += h[b][j] * w[j];
        out[b * 2 + o] = acc;
    }
}

// ---------------- host launch ----------------
extern "C" void kernel_launch(void* const* d_in, const int* in_sizes, int n_in,
                              void* d_out, int out_size) {
    const float *x_seq = 0, *W1 = 0, *as1 = 0, *ad1 = 0, *b1 = 0;
    const float *W2 = 0, *as2 = 0, *ad2 = 0, *b2 = 0;
    const float *W3 = 0, *as3 = 0, *ad3 = 0, *b3 = 0;
    const float *W4 = 0, *as4 = 0, *ad4 = 0, *b4 = 0;
    const float *w_ih = 0, *w_hh = 0, *b_ih = 0, *b_hh = 0, *w_fc = 0, *b_fc = 0;
    const int *edge = 0;
    int c1024 = 0, c512 = 0, c256 = 0, c128 = 0, c8 = 0;
    for (int i = 0; i < n_in; i++) {
        const float* p = (const float*)d_in[i];
        switch (in_sizes[i]) {
            case 172800: x_seq = p; break;
            case 276480: edge = (const int*)p; break;
            case 8640:   break;
            case 131072: W2 = p; break;
            case 65536:  w_hh = p; break;
            case 32768:  W3 = p; break;
            case 4096:   w_ih = p; break;
            case 1024:   { if (c1024++ == 0) W1 = p; else W4 = p; } break;
            case 512: { int k = c512++;
                if (k == 0) as1 = p; else if (k == 1) ad1 = p; else if (k == 2) b1 = p;
                else if (k == 3) b_ih = p; else b_hh = p; } break;
            case 256: { int k = c256++;
                if (k == 0) as2 = p; else if (k == 1) ad2 = p; else if (k == 2) b2 = p;
                else w_fc = p; } break;
            case 128: { int k = c128++;
                if (k == 0) as3 = p; else if (k == 1) ad3 = p; else b3 = p; } break;
            case 8: { int k = c8++;
                if (k == 0) as4 = p; else if (k == 1) ad4 = p; else b4 = p; } break;
            case 2: b_fc = p; break;
            default: break;
        }
    }
    const int* src = edge;

    float *bufA, *bufB;
    __nv_bfloat16 *X1hi, *X1lo, *Xhi, *Xlo, *W2hi, *W2lo, *W3hi, *W3lo;
    cudaGetSymbolAddress((void**)&bufA, g_bufA);
    cudaGetSymbolAddress((void**)&bufB, g_bufB);
    cudaGetSymbolAddress((void**)&X1hi, g_X1hi);
    cudaGetSymbolAddress((void**)&X1lo, g_X1lo);
    cudaGetSymbolAddress((void**)&Xhi, g_Xhi);
    cudaGetSymbolAddress((void**)&Xlo, g_Xlo);
    cudaGetSymbolAddress((void**)&W2hi, g_W2hi);
    cudaGetSymbolAddress((void**)&W2lo, g_W2lo);
    cudaGetSymbolAddress((void**)&W3hi, g_W3hi);
    cudaGetSymbolAddress((void**)&W3lo, g_W3lo);

    const int SM_L1  = (NPG * 2 + NPG * 8 * 2 + NPG * 16 + 1024 + 512) * 4;   // 153024
    const int SM_F32 = (NPG * 32 + NPG * 2 + NPG * 17) * 4;                   // 220320
    const int SM_F16 = (NPG * 16 + NPG * 2 + NPG * 17 + NPG * 16) * 4;        // 220320
    const int SM_F8  = (NPG * 8  + NPG * 2 + NPG * 17 + NPG * 16) * 4;        // 185760
    cudaFuncSetAttribute(l1_fused, cudaFuncAttributeMaxDynamicSharedMemorySize, SM_L1);
    cudaFuncSetAttribute(fused_gat<8, 32, false, true>, cudaFuncAttributeMaxDynamicSharedMemorySize, SM_F32);
    cudaFuncSetAttribute(fused_gat<8, 16, true, false>, cudaFuncAttributeMaxDynamicSharedMemorySize, SM_F16);
    cudaFuncSetAttribute(fused_gat<1, 8, true, false>,  cudaFuncAttributeMaxDynamicSharedMemorySize, SM_F8);

    // 1: localize src
    prep_lsrc<<<540, 256>>>(src);
    // 2: split W2/W3 + uvec
    setup2<<<641, 256>>>(W2, W3, W1, as1, ad1);
    // 3: layer 1 fused -> X1 split bf16
    l1_fused<<<T_STEPS * B_GR, 1024, SM_L1>>>(x_seq, W1, b1);
    // 4 (PROFILED): L2 GEMM bf16x3 -> bufA [TN,256]
    gemm_bf16<<<dim3(2, TN / 128), 256>>>(X1hi, X1lo, W2hi, W2lo, bufA, 512, 256);
    // 5: GAT layer 2 -> split bf16
    fused_gat<8, 32, false, true><<<T_STEPS * B_GR * 8, 1024, SM_F32>>>(bufA, as2, ad2, b2, nullptr);
    // 6: L3 GEMM bf16x3 -> bufA [TN,128]
    gemm_bf16<<<dim3(1, TN / 128), 256>>>(Xhi, Xlo, W3hi, W3lo, bufA, 256, 128);
    // 7: GAT layer 3 -> bufB fp32
    fused_gat<8, 16, true, false><<<T_STEPS * B_GR * 8, 1024, SM_F16>>>(bufA, as3, ad3, b3, bufB);
    // 8: L4 GEMM fp32 -> bufA [TN,8]
    gemm_l4<<<(TN * 8 + 255) / 256, 256>>>(bufB, W4, bufA);
    // 9: GAT layer 4 -> bufB [TN,8]
    fused_gat<1, 8, true, false><<<T_STEPS * B_GR, 1024, SM_F8>>>(bufA, as4, ad4, b4, bufB);
    // 10-11: pool + LSTM
    pool_kernel<<<T_STEPS * B_GR, 256>>>(bufB);
    lstm_fc<<<1, 1024>>>(w_ih, w_hh, b_ih, b_hh, w_fc, b_fc, (float*)d_out);
}

// round 8
// speedup vs baseline: 1.2051x; 1.0499x over previous
#include <cuda_runtime.h>
#include <cuda_bf16.h>
#include <math.h>

#define T_STEPS 10
#define B_GR    8
#define NPG     1080
#define N_NODES 8640
#define TN      86400
#define DEG     16

// ---------------- scratch ----------------
__device__ float g_bufA[(size_t)TN * 256];
__device__ float g_bufB[(size_t)TN * 128];
__device__ __nv_bfloat16 g_X1hi[(size_t)TN * 512];
__device__ __nv_bfloat16 g_X1lo[(size_t)TN * 512];
__device__ __nv_bfloat16 g_Xhi[(size_t)TN * 256];
__device__ __nv_bfloat16 g_Xlo[(size_t)TN * 256];
__device__ __nv_bfloat16 g_W2hi[512 * 256], g_W2lo[512 * 256];
__device__ __nv_bfloat16 g_W3hi[256 * 128], g_W3lo[256 * 128];
__device__ float g_emb[T_STEPS * B_GR * 8];
__device__ float g_uv[32];
__device__ int   g_lsrc[N_NODES * 16];

struct alignas(16) B16x8 { __nv_bfloat16 v[8]; };
struct alignas(8)  B16x4 { __nv_bfloat16 v[4]; };

__device__ __forceinline__ void split_bf16(float x, __nv_bfloat16& h, __nv_bfloat16& l) {
    h = __float2bfloat16_rn(x);
    l = __float2bfloat16_rn(x - __bfloat162float(h));
}

// ---------------- fast exp for x <= 0 ----------------
__device__ __forceinline__ float exp_neg(float x) {
    x = fmaxf(x, -87.0f);
    const float L2E = 1.4426950408889634f;
    float z = fmaf(x, L2E, 12582912.0f);
    int   ei = __float_as_int(z);
    float n = z - 12582912.0f;
    float f = fmaf(x, L2E, -n);
    float r = fmaf(1.5403530e-4f, f, 1.3333558e-3f);
    r = fmaf(r, f, 9.6181291e-3f);
    r = fmaf(r, f, 5.5504109e-2f);
    r = fmaf(r, f, 2.4022651e-1f);
    r = fmaf(r, f, 6.9314718e-1f);
    r = fmaf(r, f, 1.0f);
    float s = __int_as_float((ei + 127) << 23);
    return r * s;
}
__device__ __forceinline__ float elu_f(float v) { return v > 0.f ? v : exp_neg(v) - 1.f; }
__device__ __forceinline__ float lrelu(float e) { return e >= 0.f ? e : 0.2f * e; }

// ---------------- setup kernels ----------------
__global__ void prep_lsrc(const int* __restrict__ src) {
    int i = blockIdx.x * 256 + threadIdx.x;
    int b = i / (NPG * 16);
    g_lsrc[i] = src[i] - b * NPG;
}

__global__ void setup2(const float* __restrict__ W2, const float* __restrict__ W3,
                       const float* __restrict__ W1, const float* __restrict__ as1,
                       const float* __restrict__ ad1) {
    int bid = blockIdx.x, tid = threadIdx.x;
    if (bid < 512) {
        int i = bid * 256 + tid;
        split_bf16(W2[i], g_W2hi[i], g_W2lo[i]);
    } else if (bid < 640) {
        int i = (bid - 512) * 256 + tid;
        split_bf16(W3[i], g_W3hi[i], g_W3lo[i]);
    } else if (tid < 32) {
        int d = tid >> 4, h = (tid >> 1) & 7, f = tid & 1;
        const float* a = d ? ad1 : as1;
        float s = 0.f;
        #pragma unroll
        for (int c = 0; c < 64; c++) s += W1[f * 512 + h * 64 + c] * a[h * 64 + c];
        g_uv[tid] = s;
    }
}

// ---------------- layer 1 fully fused: x -> X1 (split bf16) ----------------
__global__ __launch_bounds__(1024, 1)
void l1_fused(const float* __restrict__ x, const float* __restrict__ W1,
              const float* __restrict__ b1) {
    extern __shared__ float sm[];
    float* xs   = sm;
    float* es_s = xs + NPG * 2;
    float* ed_s = es_s + NPG * 8;
    float* zS   = ed_s + NPG * 8;
    float* W1s  = zS + NPG * 16;
    float* b1s  = W1s + 1024;
    __shared__ float uvS[32];
    int tb = blockIdx.x;
    int b = tb & 7, t = tb >> 3;
    int base = t * N_NODES + b * NPG;
    int tid = threadIdx.x;
    if (tid < 32) uvS[tid] = g_uv[tid];
    for (int i = tid; i < 1024; i += 1024) W1s[i] = W1[i];
    if (tid < 512) b1s[tid] = b1[tid];
    for (int i = tid; i < NPG * 2; i += 1024) xs[i] = x[(size_t)base * 2 + i];
    __syncthreads();
    for (int task = tid; task < NPG * 8; task += 1024) {
        int n = task >> 3, h = task & 7;
        float x0 = xs[n * 2], x1 = xs[n * 2 + 1];
        es_s[task] = fmaf(x0, uvS[h * 2], x1 * uvS[h * 2 + 1]);
        ed_s[task] = fmaf(x0, uvS[16 + h * 2], x1 * uvS[16 + h * 2 + 1]);
    }
    __syncthreads();
    for (int task = tid; task < NPG * 8; task += 1024) {
        int n = task >> 3, h = task & 7;
        const int4* ls4 = (const int4*)(g_lsrc + ((size_t)b * NPG + n) * 16);
        int4 iA = ls4[0], iB = ls4[1], iC = ls4[2], iD = ls4[3];
        int idxs[16] = {iA.x, iA.y, iA.z, iA.w, iB.x, iB.y, iB.z, iB.w,
                        iC.x, iC.y, iC.z, iC.w, iD.x, iD.y, iD.z, iD.w};
        float ed = ed_s[task];
        float ev[17];
        float m = -1e30f;
        #pragma unroll
        for (int k = 0; k < 16; k++) {
            float e = lrelu(es_s[idxs[k] * 8 + h] + ed);
            ev[k] = e; m = fmaxf(m, e);
        }
        { float e = lrelu(es_s[task] + ed); ev[16] = e; m = fmaxf(m, e); }
        float ssum = 0.f;
        #pragma unroll
        for (int k = 0; k < 17; k++) { float v = exp_neg(ev[k] - m); ev[k] = v; ssum += v; }
        float inv = 1.f / (ssum + 1e-16f);
        float z0 = 0.f, z1 = 0.f;
        #pragma unroll
        for (int k = 0; k < 16; k++) {
            float a = ev[k] * inv;
            z0 = fmaf(a, xs[idxs[k] * 2], z0);
            z1 = fmaf(a, xs[idxs[k] * 2 + 1], z1);
        }
        {
            float a = ev[16] * inv;
            z0 = fmaf(a, xs[n * 2], z0);
            z1 = fmaf(a, xs[n * 2 + 1], z1);
        }
        zS[n * 16 + h * 2] = z0;
        zS[n * 16 + h * 2 + 1] = z1;
    }
    __syncthreads();
    for (int i = tid; i < NPG * 64; i += 1024) {
        int n = i >> 6, kg = i & 63;
        int k0 = kg * 8, h = kg >> 3;
        float z0 = zS[n * 16 + h * 2], z1 = zS[n * 16 + h * 2 + 1];
        B16x8 hv, lv;
        #pragma unroll
        for (int j = 0; j < 8; j++) {
            int k = k0 + j;
            float v = elu_f(fmaf(z0, W1s[k], fmaf(z1, W1s[512 + k], b1s[k])));
            split_bf16(v, hv.v[j], lv.v[j]);
        }
        size_t off = (size_t)(base + n) * 512 + k0;
        *(B16x8*)(g_X1hi + off) = hv;
        *(B16x8*)(g_X1lo + off) = lv;
    }
}

// ---------------- bf16x3 tensor-core GEMM with ldmatrix, 512 threads ----------------
#define MMA_BF16(d, a, b0, b1) \
    asm volatile("mma.sync.aligned.m16n8k16.row.col.f32.bf16.bf16.f32 " \
        "{%0,%1,%2,%3}, {%4,%5,%6,%7}, {%8,%9}, {%0,%1,%2,%3};" \
        : "+f"(d[0]), "+f"(d[1]), "+f"(d[2]), "+f"(d[3]) \
        : "r"(a[0]), "r"(a[1]), "r"(a[2]), "r"(a[3]), "r"(b0), "r"(b1))

#define LDMX4(r, addr) \
    asm volatile("ldmatrix.sync.aligned.m8n8.x4.shared.b16 {%0,%1,%2,%3}, [%4];" \
        : "=r"(r[0]), "=r"(r[1]), "=r"(r[2]), "=r"(r[3]) : "r"(addr))

#define LDMX4T(r, addr) \
    asm volatile("ldmatrix.sync.aligned.m8n8.x4.trans.shared.b16 {%0,%1,%2,%3}, [%4];" \
        : "=r"(r[0]), "=r"(r[1]), "=r"(r[2]), "=r"(r[3]) : "r"(addr))

#define ASTR 24    // sA row stride (shorts): 12 words -> conflict-free ldmatrix
#define BSTR2 136  // sB row stride (shorts): 68 words -> conflict-free ldmatrix.trans

__global__ __launch_bounds__(512)
void gemm_bf16(const __nv_bfloat16* __restrict__ Ahi, const __nv_bfloat16* __restrict__ Alo,
               const __nv_bfloat16* __restrict__ Whi, const __nv_bfloat16* __restrict__ Wlo,
               float* __restrict__ C, int K, int Nc) {
    __shared__ alignas(16) unsigned short sA[2][2][128 * ASTR];
    __shared__ alignas(16) unsigned short sB[2][2][16 * BSTR2];
    const int tid = threadIdx.x;
    const int lane = tid & 31, wid = tid >> 5;
    const int warpM = wid & 3, warpN = wid >> 2;     // 4M x 4N warps, 32x32 each
    const int rb = blockIdx.y * 128, cb = blockIdx.x * 128;
    // staging: 512 threads = 256 hi + 256 lo
    const int hl = tid >> 8;
    const int j = tid & 255;
    const int arow = j >> 1, aseg = j & 1;
    const int brow = j >> 4, bcol = (j & 15) * 8;
    const __nv_bfloat16* Asrc = hl ? Alo : Ahi;
    const __nv_bfloat16* Bsrc = hl ? Wlo : Whi;

    float acc[2][4][4] = {};

    {   // prologue
        uint4 va = *(const uint4*)(Asrc + (size_t)(rb + arow) * K + aseg * 8);
        uint4 vb = *(const uint4*)(Bsrc + (size_t)brow * Nc + cb + bcol);
        *(uint4*)&sA[0][hl][arow * ASTR + aseg * 8] = va;
        *(uint4*)&sB[0][hl][brow * BSTR2 + bcol] = vb;
    }
    __syncthreads();

    // fragment load addresses (lane-fixed offsets)
    const int a_r = (lane & 15);
    const int a_c = (lane >> 4) * 8;
    const int b_k = (lane & 7) + (lane & 8);
    const int b_n = (lane & 16) >> 1;

    const int nk = K >> 4;
    for (int ck = 0; ck < nk; ck++) {
        int p = ck & 1;
        uint4 va, vb;
        bool more = (ck + 1) < nk;
        if (more) {
            int k0 = (ck + 1) << 4;
            va = *(const uint4*)(Asrc + (size_t)(rb + arow) * K + k0 + aseg * 8);
            vb = *(const uint4*)(Bsrc + (size_t)(k0 + brow) * Nc + cb + bcol);
        }
        unsigned ah[2][4], al[2][4];
        #pragma unroll
        for (int ma = 0; ma < 2; ma++) {
            int r = warpM * 32 + ma * 16 + a_r;
            unsigned adh = (unsigned)__cvta_generic_to_shared(&sA[p][0][r * ASTR + a_c]);
            unsigned adl = (unsigned)__cvta_generic_to_shared(&sA[p][1][r * ASTR + a_c]);
            LDMX4(ah[ma], adh);
            LDMX4(al[ma], adl);
        }
        unsigned bh[4][2], bl[4][2];
        #pragma unroll
        for (int g = 0; g < 2; g++) {
            int n0 = warpN * 32 + g * 16 + b_n;
            unsigned adh = (unsigned)__cvta_generic_to_shared(&sB[p][0][b_k * BSTR2 + n0]);
            unsigned adl = (unsigned)__cvta_generic_to_shared(&sB[p][1][b_k * BSTR2 + n0]);
            unsigned th[4], tl[4];
            LDMX4T(th, adh);
            LDMX4T(tl, adl);
            bh[g * 2][0] = th[0]; bh[g * 2][1] = th[1];
            bh[g * 2 + 1][0] = th[2]; bh[g * 2 + 1][1] = th[3];
            bl[g * 2][0] = tl[0]; bl[g * 2][1] = tl[1];
            bl[g * 2 + 1][0] = tl[2]; bl[g * 2 + 1][1] = tl[3];
        }
        #pragma unroll
        for (int ma = 0; ma < 2; ma++)
            #pragma unroll
            for (int na = 0; na < 4; na++) {
                MMA_BF16(acc[ma][na], ah[ma], bh[na][0], bh[na][1]);
                MMA_BF16(acc[ma][na], ah[ma], bl[na][0], bl[na][1]);
                MMA_BF16(acc[ma][na], al[ma], bh[na][0], bh[na][1]);
            }
        __syncthreads();
        if (more) {
            int q = p ^ 1;
            *(uint4*)&sA[q][hl][arow * ASTR + aseg * 8] = va;
            *(uint4*)&sB[q][hl][brow * BSTR2 + bcol] = vb;
            __syncthreads();
        }
    }
    #pragma unroll
    for (int ma = 0; ma < 2; ma++)
        #pragma unroll
        for (int na = 0; na < 4; na++) {
            int r0 = rb + warpM * 32 + ma * 16 + (lane >> 2);
            int c = cb + warpN * 32 + na * 8 + (lane & 3) * 2;
            *(float2*)(C + (size_t)r0 * Nc + c)       = make_float2(acc[ma][na][0], acc[ma][na][1]);
            *(float2*)(C + (size_t)(r0 + 8) * Nc + c) = make_float2(acc[ma][na][2], acc[ma][na][3]);
        }
}

// ---------------- L4 GEMM (fp32, tiny) ----------------
__global__ void gemm_l4(const float* __restrict__ X, const float* __restrict__ W4,
                        float* __restrict__ Y) {
    __shared__ float w[1024];
    int tid = threadIdx.x;
    for (int i = tid; i < 1024; i += blockDim.x) w[i] = W4[i];
    __syncthreads();
    int idx = blockIdx.x * blockDim.x + tid;
    if (idx >= TN * 8) return;
    int row = idx >> 3, j = idx & 7;
    const float4* xr = (const float4*)(X + (size_t)row * 128);
    float acc = 0.f;
    #pragma unroll 8
    for (int k = 0; k < 32; k++) {
        float4 v = xr[k];
        acc = fmaf(v.x, w[(k * 4 + 0) * 8 + j], acc);
        acc = fmaf(v.y, w[(k * 4 + 1) * 8 + j], acc);
        acc = fmaf(v.z, w[(k * 4 + 2) * 8 + j], acc);
        acc = fmaf(v.w, w[(k * 4 + 3) * 8 + j], acc);
    }
    Y[idx] = acc;
}

// ---------------- fully fused GAT ----------------
template<int H, int C, bool LSRC_SMEM, bool OUT_SPLIT>
__global__ __launch_bounds__(1024, 1)
void fused_gat(const float* __restrict__ Y, const float* __restrict__ as_,
               const float* __restrict__ ad_, const float* __restrict__ bias,
               float* __restrict__ Xout) {
    extern __shared__ float sm[];
    constexpr int HC = H * C;
    constexpr int Q = C / 4;
    float* tile   = sm;
    float* es_s   = tile + NPG * C;
    float* ed_s   = es_s + NPG;
    float* alphaS = ed_s + NPG;
    int*   lsrcS  = (int*)(alphaS + NPG * 17);
    __shared__ float as_s[C], ad_s[C], bi_s[C];
    int blk = blockIdx.x;
    int h = (H == 1) ? 0 : (blk % H);
    int tb = (H == 1) ? blk : (blk / H);
    int b = tb % B_GR;
    int t = tb / B_GR;
    int base = t * N_NODES + b * NPG;
    int tid = threadIdx.x;
    const int* lg = g_lsrc + (size_t)b * NPG * 16;
    if (tid < C) { as_s[tid] = as_[h * C + tid]; ad_s[tid] = ad_[h * C + tid]; bi_s[tid] = bias[h * C + tid]; }
    for (int i = tid; i < NPG * Q; i += blockDim.x) {
        int n = i / Q, q = i % Q;
        *(float4*)&tile[n * C + q * 4] =
            *(const float4*)(Y + (size_t)(base + n) * HC + h * C + q * 4);
    }
    if (LSRC_SMEM) {
        for (int i = tid; i < NPG * 4; i += blockDim.x)
            ((int4*)lsrcS)[i] = ((const int4*)lg)[i];
    }
    __syncthreads();
    for (int n = tid; n < NPG; n += blockDim.x) {
        const float* tn = tile + n * C;
        int rot1 = tid & (Q - 1);
        float se = 0.f, de = 0.f;
        #pragma unroll
        for (int jj = 0; jj < Q; jj++) {
            int q = (jj + rot1) & (Q - 1);
            float4 v = *(const float4*)&tn[q * 4];
            float4 a = *(const float4*)&as_s[q * 4];
            float4 d = *(const float4*)&ad_s[q * 4];
            se = fmaf(v.x, a.x, fmaf(v.y, a.y, fmaf(v.z, a.z, fmaf(v.w, a.w, se))));
            de = fmaf(v.x, d.x, fmaf(v.y, d.y, fmaf(v.z, d.z, fmaf(v.w, d.w, de))));
        }
        es_s[n] = se; ed_s[n] = de;
    }
    __syncthreads();
    for (int n = tid; n < NPG; n += blockDim.x) {
        const int4* ls4 = LSRC_SMEM ? (const int4*)(lsrcS + n * 16)
                                    : (const int4*)(lg + n * 16);
        int4 iA = ls4[0], iB = ls4[1], iC_ = ls4[2], iD = ls4[3];
        int idxs[16] = {iA.x, iA.y, iA.z, iA.w, iB.x, iB.y, iB.z, iB.w,
                        iC_.x, iC_.y, iC_.z, iC_.w, iD.x, iD.y, iD.z, iD.w};
        float ed = ed_s[n];
        float m = lrelu(es_s[n] + ed);
        #pragma unroll
        for (int k = 0; k < 16; k++) m = fmaxf(m, lrelu(es_s[idxs[k]] + ed));
        float* ap = alphaS + n * 17;
        float ssum = 0.f;
        #pragma unroll
        for (int k = 0; k < 16; k++) {
            float v = exp_neg(lrelu(es_s[idxs[k]] + ed) - m);
            ap[k] = v; ssum += v;
        }
        { float v = exp_neg(lrelu(es_s[n] + ed) - m); ap[16] = v; ssum += v; }
        float inv = 1.f / (ssum + 1e-16f);
        #pragma unroll
        for (int k = 0; k < 17; k++) ap[k] *= inv;
    }
    __syncthreads();
    for (int task = tid; task < NPG * Q; task += blockDim.x) {
        int n = task / Q, q = task % Q;
        const float* ap = alphaS + n * 17;
        const int* ls = LSRC_SMEM ? (lsrcS + n * 16) : (lg + n * 16);
        float4 acc = make_float4(0.f, 0.f, 0.f, 0.f);
        #pragma unroll
        for (int k = 0; k < 16; k++) {
            int idx = ls[k];
            float a = ap[k];
            float4 v = *(const float4*)&tile[idx * C + q * 4];
            acc.x = fmaf(a, v.x, acc.x); acc.y = fmaf(a, v.y, acc.y);
            acc.z = fmaf(a, v.z, acc.z); acc.w = fmaf(a, v.w, acc.w);
        }
        {
            float a = ap[16];
            float4 v = *(const float4*)&tile[n * C + q * 4];
            acc.x = fmaf(a, v.x, acc.x); acc.y = fmaf(a, v.y, acc.y);
            acc.z = fmaf(a, v.z, acc.z); acc.w = fmaf(a, v.w, acc.w);
        }
        float o0 = elu_f(acc.x + bi_s[q * 4 + 0]);
        float o1 = elu_f(acc.y + bi_s[q * 4 + 1]);
        float o2 = elu_f(acc.z + bi_s[q * 4 + 2]);
        float o3 = elu_f(acc.w + bi_s[q * 4 + 3]);
        size_t off = (size_t)(base + n) * HC + h * C + q * 4;
        if (OUT_SPLIT) {
            B16x4 hv, lv;
            split_bf16(o0, hv.v[0], lv.v[0]);
            split_bf16(o1, hv.v[1], lv.v[1]);
            split_bf16(o2, hv.v[2], lv.v[2]);
            split_bf16(o3, hv.v[3], lv.v[3]);
            *(B16x4*)(g_Xhi + off) = hv;
            *(B16x4*)(g_Xlo + off) = lv;
        } else {
            *(float4*)(Xout + off) = make_float4(o0, o1, o2, o3);
        }
    }
}

// ---------------- mean pool ----------------
__global__ void pool_kernel(const float* __restrict__ X4) {
    int tb = blockIdx.x;
    int t = tb / B_GR, b = tb % B_GR;
    int tid = threadIdx.x;
    float acc[8] = {};
    for (int nn = tid; nn < NPG; nn += blockDim.x) {
        const float* p = X4 + ((size_t)(t * N_NODES + b * NPG + nn)) * 8;
        #pragma unroll
        for (int f = 0; f < 8; f++) acc[f] += p[f];
    }
    __shared__ float s[8];
    if (tid < 8) s[tid] = 0.f;
    __syncthreads();
    #pragma unroll
    for (int f = 0; f < 8; f++) atomicAdd(&s[f], acc[f]);
    __syncthreads();
    if (tid < 8) g_emb[tb * 8 + tid] = s[tid] * (1.0f / (float)NPG);
}

// ---------------- LSTM + FC ----------------
__device__ __forceinline__ float sigmoidf(float x) { return 1.f / (1.f + expf(-x)); }

__global__ void lstm_fc(const float* __restrict__ w_ih, const float* __restrict__ w_hh,
                        const float* __restrict__ b_ih, const float* __restrict__ b_hh,
                        const float* __restrict__ w_fc, const float* __restrict__ b_fc,
                        float* __restrict__ out) {
    __shared__ float h[8][128], c[8][128], g[8][512], xs[8][8];
    int tid = threadIdx.x;
    for (int i = tid; i < 8 * 128; i += 1024) { ((float*)h)[i] = 0.f; ((float*)c)[i] = 0.f; }
    __syncthreads();
    for (int t = 0; t < T_STEPS; t++) {
        if (tid < 64) xs[tid >> 3][tid & 7] = g_emb[t * 64 + tid];
        __syncthreads();
        #pragma unroll
        for (int task = tid; task < 4096; task += 1024) {
            int b = task >> 9, row = task & 511;
            float acc = b_ih[row] + b_hh[row];
            const float* wi = w_ih + row * 8;
            #pragma unroll
            for (int k = 0; k < 8; k++) acc += xs[b][k] * wi[k];
            const float4* wh = (const float4*)(w_hh + row * 128);
            const float4* hb = (const float4*)h[b];
            #pragma unroll 8
            for (int jj = 0; jj < 32; jj++) {
                float4 w4 = wh[jj], h4 = hb[jj];
                acc = fmaf(w4.x, h4.x, acc); acc = fmaf(w4.y, h4.y, acc);
                acc = fmaf(w4.z, h4.z, acc); acc = fmaf(w4.w, h4.w, acc);
            }
            g[b][row] = acc;
        }
        __syncthreads();
        if (tid < 1024) {
            int b = tid >> 7, u = tid & 127;
            float ig = sigmoidf(g[b][u]);
            float fg = sigmoidf(g[b][128 + u]);
            float gg = tanhf(g[b][256 + u]);
            float og = sigmoidf(g[b][384 + u]);
            float cn = fg * c[b][u] + ig * gg;
            c[b][u] = cn;
            h[b][u] = og * tanhf(cn);
        }
        __syncthreads();
    }
    if (tid < 16) {
        int b = tid >> 1, o = tid & 1;
        float acc = b_fc[o];
        const float* w = w_fc + o * 128;
        #pragma unroll 8
        for (int jj = 0; jj < 128; jj++) acc += h[b][jj] * w[jj];
        out[b * 2 + o] = acc;
    }
}

// ---------------- host launch ----------------
extern "C" void kernel_launch(void* const* d_in, const int* in_sizes, int n_in,
                              void* d_out, int out_size) {
    const float *x_seq = 0, *W1 = 0, *as1 = 0, *ad1 = 0, *b1 = 0;
    const float *W2 = 0, *as2 = 0, *ad2 = 0, *b2 = 0;
    const float *W3 = 0, *as3 = 0, *ad3 = 0, *b3 = 0;
    const float *W4 = 0, *as4 = 0, *ad4 = 0, *b4 = 0;
    const float *w_ih = 0, *w_hh = 0, *b_ih = 0, *b_hh = 0, *w_fc = 0, *b_fc = 0;
    const int *edge = 0;
    int c1024 = 0, c512 = 0, c256 = 0, c128 = 0, c8 = 0;
    for (int i = 0; i < n_in; i++) {
        const float* p = (const float*)d_in[i];
        switch (in_sizes[i]) {
            case 172800: x_seq = p; break;
            case 276480: edge = (const int*)p; break;
            case 8640:   break;
            case 131072: W2 = p; break;
            case 65536:  w_hh = p; break;
            case 32768:  W3 = p; break;
            case 4096:   w_ih = p; break;
            case 1024:   { if (c1024++ == 0) W1 = p; else W4 = p; } break;
            case 512: { int k = c512++;
                if (k == 0) as1 = p; else if (k == 1) ad1 = p; else if (k == 2) b1 = p;
                else if (k == 3) b_ih = p; else b_hh = p; } break;
            case 256: { int k = c256++;
                if (k == 0) as2 = p; else if (k == 1) ad2 = p; else if (k == 2) b2 = p;
                else w_fc = p; } break;
            case 128: { int k = c128++;
                if (k == 0) as3 = p; else if (k == 1) ad3 = p; else b3 = p; } break;
            case 8: { int k = c8++;
                if (k == 0) as4 = p; else if (k == 1) ad4 = p; else b4 = p; } break;
            case 2: b_fc = p; break;
            default: break;
        }
    }
    const int* src = edge;

    float *bufA, *bufB;
    __nv_bfloat16 *X1hi, *X1lo, *Xhi, *Xlo, *W2hi, *W2lo, *W3hi, *W3lo;
    cudaGetSymbolAddress((void**)&bufA, g_bufA);
    cudaGetSymbolAddress((void**)&bufB, g_bufB);
    cudaGetSymbolAddress((void**)&X1hi, g_X1hi);
    cudaGetSymbolAddress((void**)&X1lo, g_X1lo);
    cudaGetSymbolAddress((void**)&Xhi, g_Xhi);
    cudaGetSymbolAddress((void**)&Xlo, g_Xlo);
    cudaGetSymbolAddress((void**)&W2hi, g_W2hi);
    cudaGetSymbolAddress((void**)&W2lo, g_W2lo);
    cudaGetSymbolAddress((void**)&W3hi, g_W3hi);
    cudaGetSymbolAddress((void**)&W3lo, g_W3lo);

    const int SM_L1  = (NPG * 2 + NPG * 8 * 2 + NPG * 16 + 1024 + 512) * 4;
    const int SM_F32 = (NPG * 32 + NPG * 2 + NPG * 17) * 4;
    const int SM_F16 = (NPG * 16 + NPG * 2 + NPG * 17 + NPG * 16) * 4;
    const int SM_F8  = (NPG * 8  + NPG * 2 + NPG * 17 + NPG * 16) * 4;
    cudaFuncSetAttribute(l1_fused, cudaFuncAttributeMaxDynamicSharedMemorySize, SM_L1);
    cudaFuncSetAttribute(fused_gat<8, 32, false, true>, cudaFuncAttributeMaxDynamicSharedMemorySize, SM_F32);
    cudaFuncSetAttribute(fused_gat<8, 16, true, false>, cudaFuncAttributeMaxDynamicSharedMemorySize, SM_F16);
    cudaFuncSetAttribute(fused_gat<1, 8, true, false>,  cudaFuncAttributeMaxDynamicSharedMemorySize, SM_F8);

    // 1: localize src
    prep_lsrc<<<540, 256>>>(src);
    // 2: split W2/W3 + uvec
    setup2<<<641, 256>>>(W2, W3, W1, as1, ad1);
    // 3: layer 1 fused -> X1 split bf16
    l1_fused<<<T_STEPS * B_GR, 1024, SM_L1>>>(x_seq, W1, b1);
    // 4 (PROFILED): L2 GEMM bf16x3+ldmatrix -> bufA [TN,256]
    gemm_bf16<<<dim3(2, TN / 128), 512>>>(X1hi, X1lo, W2hi, W2lo, bufA, 512, 256);
    // 5: GAT layer 2 -> split bf16
    fused_gat<8, 32, false, true><<<T_STEPS * B_GR * 8, 1024, SM_F32>>>(bufA, as2, ad2, b2, nullptr);
    // 6: L3 GEMM
    gemm_bf16<<<dim3(1, TN / 128), 512>>>(Xhi, Xlo, W3hi, W3lo, bufA, 256, 128);
    // 7: GAT layer 3 -> bufB fp32
    fused_gat<8, 16, true, false><<<T_STEPS * B_GR * 8, 1024, SM_F16>>>(bufA, as3, ad3, b3, bufB);
    // 8: L4 GEMM fp32
    gemm_l4<<<(TN * 8 + 255) / 256, 256>>>(bufB, W4, bufA);
    // 9: GAT layer 4
    fused_gat<1, 8, true, false><<<T_STEPS * B_GR, 1024, SM_F8>>>(bufA, as4, ad4, b4, bufB);
    // 10-11: pool + LSTM
    pool_kernel<<<T_STEPS * B_GR, 256>>>(bufB);
    lstm_fc<<<1, 1024>>>(w_ih, w_hh, b_ih, b_hh, w_fc, b_fc, (float*)d_out);
}

// round 9
// speedup vs baseline: 1.2200x; 1.0123x over previous
#include <cuda_runtime.h>
#include <cuda_bf16.h>
#include <math.h>

#define T_STEPS 10
#define B_GR    8
#define NPG     1080
#define N_NODES 8640
#define TN      86400
#define DEG     16

// ---------------- scratch ----------------
__device__ float g_bufA[(size_t)TN * 256];
__device__ float g_bufB[(size_t)TN * 128];
__device__ __nv_bfloat16 g_X1hi[(size_t)TN * 512];
__device__ __nv_bfloat16 g_X1lo[(size_t)TN * 512];
__device__ __nv_bfloat16 g_Xhi[(size_t)TN * 256];
__device__ __nv_bfloat16 g_Xlo[(size_t)TN * 256];
__device__ __nv_bfloat16 g_W2hi[512 * 256], g_W2lo[512 * 256];
__device__ __nv_bfloat16 g_W3hi[256 * 128], g_W3lo[256 * 128];
__device__ float g_emb[T_STEPS * B_GR * 8];
__device__ float g_uv[32];
__device__ int   g_lsrc[N_NODES * 16];

struct alignas(16) B16x8 { __nv_bfloat16 v[8]; };
struct alignas(8)  B16x4 { __nv_bfloat16 v[4]; };

__device__ __forceinline__ void split_bf16(float x, __nv_bfloat16& h, __nv_bfloat16& l) {
    h = __float2bfloat16_rn(x);
    l = __float2bfloat16_rn(x - __bfloat162float(h));
}

// ---------------- fast exp for x <= 0 ----------------
__device__ __forceinline__ float exp_neg(float x) {
    x = fmaxf(x, -87.0f);
    const float L2E = 1.4426950408889634f;
    float z = fmaf(x, L2E, 12582912.0f);
    int   ei = __float_as_int(z);
    float n = z - 12582912.0f;
    float f = fmaf(x, L2E, -n);
    float r = fmaf(1.5403530e-4f, f, 1.3333558e-3f);
    r = fmaf(r, f, 9.6181291e-3f);
    r = fmaf(r, f, 5.5504109e-2f);
    r = fmaf(r, f, 2.4022651e-1f);
    r = fmaf(r, f, 6.9314718e-1f);
    r = fmaf(r, f, 1.0f);
    float s = __int_as_float((ei + 127) << 23);
    return r * s;
}
__device__ __forceinline__ float elu_f(float v) { return v > 0.f ? v : exp_neg(v) - 1.f; }
__device__ __forceinline__ float lrelu(float e) { return e >= 0.f ? e : 0.2f * e; }

// ---------------- merged setup: lsrc + W2/W3 split + uvec ----------------
__global__ void setup_all(const int* __restrict__ src, const float* __restrict__ W2,
                          const float* __restrict__ W3, const float* __restrict__ W1,
                          const float* __restrict__ as1, const float* __restrict__ ad1) {
    int bid = blockIdx.x, tid = threadIdx.x;
    if (bid < 540) {
        int i = bid * 256 + tid;
        int b = i / (NPG * 16);
        g_lsrc[i] = src[i] - b * NPG;
    } else if (bid < 1052) {
        int i = (bid - 540) * 256 + tid;
        split_bf16(W2[i], g_W2hi[i], g_W2lo[i]);
    } else if (bid < 1180) {
        int i = (bid - 1052) * 256 + tid;
        split_bf16(W3[i], g_W3hi[i], g_W3lo[i]);
    } else if (tid < 32) {
        int d = tid >> 4, h = (tid >> 1) & 7, f = tid & 1;
        const float* a = d ? ad1 : as1;
        float s = 0.f;
        #pragma unroll
        for (int c = 0; c < 64; c++) s += W1[f * 512 + h * 64 + c] * a[h * 64 + c];
        g_uv[tid] = s;
    }
}

// ---------------- layer 1 fully fused: x -> X1 (split bf16) ----------------
__global__ __launch_bounds__(1024, 1)
void l1_fused(const float* __restrict__ x, const float* __restrict__ W1,
              const float* __restrict__ b1) {
    extern __shared__ float sm[];
    float* xs   = sm;
    float* es_s = xs + NPG * 2;
    float* ed_s = es_s + NPG * 8;
    float* zS   = ed_s + NPG * 8;
    float* W1s  = zS + NPG * 16;
    float* b1s  = W1s + 1024;
    __shared__ float uvS[32];
    int tb = blockIdx.x;
    int b = tb & 7, t = tb >> 3;
    int base = t * N_NODES + b * NPG;
    int tid = threadIdx.x;
    if (tid < 32) uvS[tid] = g_uv[tid];
    for (int i = tid; i < 1024; i += 1024) W1s[i] = W1[i];
    if (tid < 512) b1s[tid] = b1[tid];
    for (int i = tid; i < NPG * 2; i += 1024) xs[i] = x[(size_t)base * 2 + i];
    __syncthreads();
    for (int task = tid; task < NPG * 8; task += 1024) {
        int n = task >> 3, h = task & 7;
        float x0 = xs[n * 2], x1 = xs[n * 2 + 1];
        es_s[task] = fmaf(x0, uvS[h * 2], x1 * uvS[h * 2 + 1]);
        ed_s[task] = fmaf(x0, uvS[16 + h * 2], x1 * uvS[16 + h * 2 + 1]);
    }
    __syncthreads();
    for (int task = tid; task < NPG * 8; task += 1024) {
        int n = task >> 3, h = task & 7;
        const int4* ls4 = (const int4*)(g_lsrc + ((size_t)b * NPG + n) * 16);
        int4 iA = ls4[0], iB = ls4[1], iC = ls4[2], iD = ls4[3];
        int idxs[16] = {iA.x, iA.y, iA.z, iA.w, iB.x, iB.y, iB.z, iB.w,
                        iC.x, iC.y, iC.z, iC.w, iD.x, iD.y, iD.z, iD.w};
        float ed = ed_s[task];
        float ev[17];
        float m = -1e30f;
        #pragma unroll
        for (int k = 0; k < 16; k++) {
            float e = lrelu(es_s[idxs[k] * 8 + h] + ed);
            ev[k] = e; m = fmaxf(m, e);
        }
        { float e = lrelu(es_s[task] + ed); ev[16] = e; m = fmaxf(m, e); }
        float ssum = 0.f;
        #pragma unroll
        for (int k = 0; k < 17; k++) { float v = exp_neg(ev[k] - m); ev[k] = v; ssum += v; }
        float inv = 1.f / (ssum + 1e-16f);
        float z0 = 0.f, z1 = 0.f;
        #pragma unroll
        for (int k = 0; k < 16; k++) {
            float a = ev[k] * inv;
            z0 = fmaf(a, xs[idxs[k] * 2], z0);
            z1 = fmaf(a, xs[idxs[k] * 2 + 1], z1);
        }
        {
            float a = ev[16] * inv;
            z0 = fmaf(a, xs[n * 2], z0);
            z1 = fmaf(a, xs[n * 2 + 1], z1);
        }
        zS[n * 16 + h * 2] = z0;
        zS[n * 16 + h * 2 + 1] = z1;
    }
    __syncthreads();
    for (int i = tid; i < NPG * 64; i += 1024) {
        int n = i >> 6, kg = i & 63;
        int k0 = kg * 8, h = kg >> 3;
        float z0 = zS[n * 16 + h * 2], z1 = zS[n * 16 + h * 2 + 1];
        B16x8 hv, lv;
        #pragma unroll
        for (int j = 0; j < 8; j++) {
            int k = k0 + j;
            float v = elu_f(fmaf(z0, W1s[k], fmaf(z1, W1s[512 + k], b1s[k])));
            split_bf16(v, hv.v[j], lv.v[j]);
        }
        size_t off = (size_t)(base + n) * 512 + k0;
        *(B16x8*)(g_X1hi + off) = hv;
        *(B16x8*)(g_X1lo + off) = lv;
    }
}

// ---------------- bf16x3 tensor-core GEMM, cp.async 3-stage pipeline ----------------
#define MMA_BF16(d, a, b0, b1) \
    asm volatile("mma.sync.aligned.m16n8k16.row.col.f32.bf16.bf16.f32 " \
        "{%0,%1,%2,%3}, {%4,%5,%6,%7}, {%8,%9}, {%0,%1,%2,%3};" \
        : "+f"(d[0]), "+f"(d[1]), "+f"(d[2]), "+f"(d[3]) \
        : "r"(a[0]), "r"(a[1]), "r"(a[2]), "r"(a[3]), "r"(b0), "r"(b1))

#define LDMX4(r, addr) \
    asm volatile("ldmatrix.sync.aligned.m8n8.x4.shared.b16 {%0,%1,%2,%3}, [%4];" \
        : "=r"(r[0]), "=r"(r[1]), "=r"(r[2]), "=r"(r[3]) : "r"(addr))

#define LDMX4T(r, addr) \
    asm volatile("ldmatrix.sync.aligned.m8n8.x4.trans.shared.b16 {%0,%1,%2,%3}, [%4];" \
        : "=r"(r[0]), "=r"(r[1]), "=r"(r[2]), "=r"(r[3]) : "r"(addr))

#define CP16(dst, src) \
    asm volatile("cp.async.cg.shared.global [%0], [%1], 16;" :: "r"(dst), "l"(src))
#define CP_COMMIT asm volatile("cp.async.commit_group;")
#define CP_WAIT1  asm volatile("cp.async.wait_group 1;")
#define CP_WAIT0  asm volatile("cp.async.wait_group 0;")

#define ASTR 24    // sA row stride (shorts)
#define BSTR2 136  // sB row stride (shorts)

__global__ __launch_bounds__(512)
void gemm_bf16(const __nv_bfloat16* __restrict__ Ahi, const __nv_bfloat16* __restrict__ Alo,
               const __nv_bfloat16* __restrict__ Whi, const __nv_bfloat16* __restrict__ Wlo,
               float* __restrict__ C, int K, int Nc) {
    __shared__ alignas(16) unsigned short sA[3][2][128 * ASTR];
    __shared__ alignas(16) unsigned short sB[3][2][16 * BSTR2];
    const int tid = threadIdx.x;
    const int lane = tid & 31, wid = tid >> 5;
    const int warpM = wid & 3, warpN = wid >> 2;
    const int rb = blockIdx.y * 128, cb = blockIdx.x * 128;
    const int hl = tid >> 8;
    const int j = tid & 255;
    const int arow = j >> 1, aseg = j & 1;
    const int brow = j >> 4, bcol = (j & 15) * 8;
    const __nv_bfloat16* aptr = (hl ? Alo : Ahi) + (size_t)(rb + arow) * K + aseg * 8;
    const __nv_bfloat16* bptr = (hl ? Wlo : Whi) + (size_t)brow * Nc + cb + bcol;
    unsigned sa_dst[3], sb_dst[3];
    #pragma unroll
    for (int s = 0; s < 3; s++) {
        sa_dst[s] = (unsigned)__cvta_generic_to_shared(&sA[s][hl][arow * ASTR + aseg * 8]);
        sb_dst[s] = (unsigned)__cvta_generic_to_shared(&sB[s][hl][brow * BSTR2 + bcol]);
    }
    const int nk = K >> 4;

    // prologue: stage chunks 0,1
    CP16(sa_dst[0], aptr);
    CP16(sb_dst[0], bptr);
    CP_COMMIT;
    CP16(sa_dst[1], aptr + 16);
    CP16(sb_dst[1], bptr + (size_t)16 * Nc);
    CP_COMMIT;

    const int a_r = (lane & 15);
    const int a_c = (lane >> 4) * 8;
    const int b_k = (lane & 7) + (lane & 8);
    const int b_n = (lane & 16) >> 1;

    float acc[2][4][4] = {};

    for (int ck = 0; ck < nk; ck++) {
        if (ck + 1 < nk) { CP_WAIT1; } else { CP_WAIT0; }
        __syncthreads();
        if (ck + 2 < nk) {
            int k0 = (ck + 2) << 4;
            int buf = (ck + 2) % 3;
            CP16(sa_dst[buf], aptr + k0);
            CP16(sb_dst[buf], bptr + (size_t)k0 * Nc);
            CP_COMMIT;
        }
        int p = ck % 3;
        unsigned ah[2][4], al[2][4];
        #pragma unroll
        for (int ma = 0; ma < 2; ma++) {
            int r = warpM * 32 + ma * 16 + a_r;
            unsigned adh = (unsigned)__cvta_generic_to_shared(&sA[p][0][r * ASTR + a_c]);
            unsigned adl = (unsigned)__cvta_generic_to_shared(&sA[p][1][r * ASTR + a_c]);
            LDMX4(ah[ma], adh);
            LDMX4(al[ma], adl);
        }
        unsigned bh[4][2], bl[4][2];
        #pragma unroll
        for (int g = 0; g < 2; g++) {
            int n0 = warpN * 32 + g * 16 + b_n;
            unsigned adh = (unsigned)__cvta_generic_to_shared(&sB[p][0][b_k * BSTR2 + n0]);
            unsigned adl = (unsigned)__cvta_generic_to_shared(&sB[p][1][b_k * BSTR2 + n0]);
            unsigned th[4], tl[4];
            LDMX4T(th, adh);
            LDMX4T(tl, adl);
            bh[g * 2][0] = th[0]; bh[g * 2][1] = th[1];
            bh[g * 2 + 1][0] = th[2]; bh[g * 2 + 1][1] = th[3];
            bl[g * 2][0] = tl[0]; bl[g * 2][1] = tl[1];
            bl[g * 2 + 1][0] = tl[2]; bl[g * 2 + 1][1] = tl[3];
        }
        #pragma unroll
        for (int ma = 0; ma < 2; ma++)
            #pragma unroll
            for (int na = 0; na < 4; na++) {
                MMA_BF16(acc[ma][na], ah[ma], bh[na][0], bh[na][1]);
                MMA_BF16(acc[ma][na], ah[ma], bl[na][0], bl[na][1]);
                MMA_BF16(acc[ma][na], al[ma], bh[na][0], bh[na][1]);
            }
        __syncthreads();
    }
    #pragma unroll
    for (int ma = 0; ma < 2; ma++)
        #pragma unroll
        for (int na = 0; na < 4; na++) {
            int r0 = rb + warpM * 32 + ma * 16 + (lane >> 2);
            int c = cb + warpN * 32 + na * 8 + (lane & 3) * 2;
            *(float2*)(C + (size_t)r0 * Nc + c)       = make_float2(acc[ma][na][0], acc[ma][na][1]);
            *(float2*)(C + (size_t)(r0 + 8) * Nc + c) = make_float2(acc[ma][na][2], acc[ma][na][3]);
        }
}

// ---------------- L4 GEMM (fp32, tiny) ----------------
__global__ void gemm_l4(const float* __restrict__ X, const float* __restrict__ W4,
                        float* __restrict__ Y) {
    __shared__ float w[1024];
    int tid = threadIdx.x;
    for (int i = tid; i < 1024; i += blockDim.x) w[i] = W4[i];
    __syncthreads();
    int idx = blockIdx.x * blockDim.x + tid;
    if (idx >= TN * 8) return;
    int row = idx >> 3, j = idx & 7;
    const float4* xr = (const float4*)(X + (size_t)row * 128);
    float acc = 0.f;
    #pragma unroll 8
    for (int k = 0; k < 32; k++) {
        float4 v = xr[k];
        acc = fmaf(v.x, w[(k * 4 + 0) * 8 + j], acc);
        acc = fmaf(v.y, w[(k * 4 + 1) * 8 + j], acc);
        acc = fmaf(v.z, w[(k * 4 + 2) * 8 + j], acc);
        acc = fmaf(v.w, w[(k * 4 + 3) * 8 + j], acc);
    }
    Y[idx] = acc;
}

// ---------------- fully fused GAT ----------------
template<int H, int C, bool LSRC_SMEM, bool OUT_SPLIT>
__global__ __launch_bounds__(1024, 1)
void fused_gat(const float* __restrict__ Y, const float* __restrict__ as_,
               const float* __restrict__ ad_, const float* __restrict__ bias,
               float* __restrict__ Xout) {
    extern __shared__ float sm[];
    constexpr int HC = H * C;
    constexpr int Q = C / 4;
    float* tile   = sm;
    float* es_s   = tile + NPG * C;
    float* ed_s   = es_s + NPG;
    float* alphaS = ed_s + NPG;
    int*   lsrcS  = (int*)(alphaS + NPG * 17);
    __shared__ float as_s[C], ad_s[C], bi_s[C];
    int blk = blockIdx.x;
    int h = (H == 1) ? 0 : (blk % H);
    int tb = (H == 1) ? blk : (blk / H);
    int b = tb % B_GR;
    int t = tb / B_GR;
    int base = t * N_NODES + b * NPG;
    int tid = threadIdx.x;
    const int* lg = g_lsrc + (size_t)b * NPG * 16;
    if (tid < C) { as_s[tid] = as_[h * C + tid]; ad_s[tid] = ad_[h * C + tid]; bi_s[tid] = bias[h * C + tid]; }
    for (int i = tid; i < NPG * Q; i += blockDim.x) {
        int n = i / Q, q = i % Q;
        *(float4*)&tile[n * C + q * 4] =
            *(const float4*)(Y + (size_t)(base + n) * HC + h * C + q * 4);
    }
    if (LSRC_SMEM) {
        for (int i = tid; i < NPG * 4; i += blockDim.x)
            ((int4*)lsrcS)[i] = ((const int4*)lg)[i];
    }
    __syncthreads();
    for (int n = tid; n < NPG; n += blockDim.x) {
        const float* tn = tile + n * C;
        int rot1 = tid & (Q - 1);
        float se = 0.f, de = 0.f;
        #pragma unroll
        for (int jj = 0; jj < Q; jj++) {
            int q = (jj + rot1) & (Q - 1);
            float4 v = *(const float4*)&tn[q * 4];
            float4 a = *(const float4*)&as_s[q * 4];
            float4 d = *(const float4*)&ad_s[q * 4];
            se = fmaf(v.x, a.x, fmaf(v.y, a.y, fmaf(v.z, a.z, fmaf(v.w, a.w, se))));
            de = fmaf(v.x, d.x, fmaf(v.y, d.y, fmaf(v.z, d.z, fmaf(v.w, d.w, de))));
        }
        es_s[n] = se; ed_s[n] = de;
    }
    __syncthreads();
    for (int n = tid; n < NPG; n += blockDim.x) {
        const int4* ls4 = LSRC_SMEM ? (const int4*)(lsrcS + n * 16)
                                    : (const int4*)(lg + n * 16);
        int4 iA = ls4[0], iB = ls4[1], iC_ = ls4[2], iD = ls4[3];
        int idxs[16] = {iA.x, iA.y, iA.z, iA.w, iB.x, iB.y, iB.z, iB.w,
                        iC_.x, iC_.y, iC_.z, iC_.w, iD.x, iD.y, iD.z, iD.w};
        float ed = ed_s[n];
        float m = lrelu(es_s[n] + ed);
        #pragma unroll
        for (int k = 0; k < 16; k++) m = fmaxf(m, lrelu(es_s[idxs[k]] + ed));
        float* ap = alphaS + n * 17;
        float ssum = 0.f;
        #pragma unroll
        for (int k = 0; k < 16; k++) {
            float v = exp_neg(lrelu(es_s[idxs[k]] + ed) - m);
            ap[k] = v; ssum += v;
        }
        { float v = exp_neg(lrelu(es_s[n] + ed) - m); ap[16] = v; ssum += v; }
        float inv = 1.f / (ssum + 1e-16f);
        #pragma unroll
        for (int k = 0; k < 17; k++) ap[k] *= inv;
    }
    __syncthreads();
    for (int task = tid; task < NPG * Q; task += blockDim.x) {
        int n = task / Q, q = task % Q;
        const float* ap = alphaS + n * 17;
        const int* ls = LSRC_SMEM ? (lsrcS + n * 16) : (lg + n * 16);
        float4 acc = make_float4(0.f, 0.f, 0.f, 0.f);
        #pragma unroll
        for (int k = 0; k < 16; k++) {
            int idx = ls[k];
            float a = ap[k];
            float4 v = *(const float4*)&tile[idx * C + q * 4];
            acc.x = fmaf(a, v.x, acc.x); acc.y = fmaf(a, v.y, acc.y);
            acc.z = fmaf(a, v.z, acc.z); acc.w = fmaf(a, v.w, acc.w);
        }
        {
            float a = ap[16];
            float4 v = *(const float4*)&tile[n * C + q * 4];
            acc.x = fmaf(a, v.x, acc.x); acc.y = fmaf(a, v.y, acc.y);
            acc.z = fmaf(a, v.z, acc.z); acc.w = fmaf(a, v.w, acc.w);
        }
        float o0 = elu_f(acc.x + bi_s[q * 4 + 0]);
        float o1 = elu_f(acc.y + bi_s[q * 4 + 1]);
        float o2 = elu_f(acc.z + bi_s[q * 4 + 2]);
        float o3 = elu_f(acc.w + bi_s[q * 4 + 3]);
        size_t off = (size_t)(base + n) * HC + h * C + q * 4;
        if (OUT_SPLIT) {
            B16x4 hv, lv;
            split_bf16(o0, hv.v[0], lv.v[0]);
            split_bf16(o1, hv.v[1], lv.v[1]);
            split_bf16(o2, hv.v[2], lv.v[2]);
            split_bf16(o3, hv.v[3], lv.v[3]);
            *(B16x4*)(g_Xhi + off) = hv;
            *(B16x4*)(g_Xlo + off) = lv;
        } else {
            *(float4*)(Xout + off) = make_float4(o0, o1, o2, o3);
        }
    }
}

// ---------------- mean pool ----------------
__global__ void pool_kernel(const float* __restrict__ X4) {
    int tb = blockIdx.x;
    int t = tb / B_GR, b = tb % B_GR;
    int tid = threadIdx.x;
    float acc[8] = {};
    for (int nn = tid; nn < NPG; nn += blockDim.x) {
        const float* p = X4 + ((size_t)(t * N_NODES + b * NPG + nn)) * 8;
        #pragma unroll
        for (int f = 0; f < 8; f++) acc[f] += p[f];
    }
    __shared__ float s[8];
    if (tid < 8) s[tid] = 0.f;
    __syncthreads();
    #pragma unroll
    for (int f = 0; f < 8; f++) atomicAdd(&s[f], acc[f]);
    __syncthreads();
    if (tid < 8) g_emb[tb * 8 + tid] = s[tid] * (1.0f / (float)NPG);
}

// ---------------- LSTM + FC ----------------
__device__ __forceinline__ float sigmoidf(float x) { return 1.f / (1.f + expf(-x)); }

__global__ void lstm_fc(const float* __restrict__ w_ih, const float* __restrict__ w_hh,
                        const float* __restrict__ b_ih, const float* __restrict__ b_hh,
                        const float* __restrict__ w_fc, const float* __restrict__ b_fc,
                        float* __restrict__ out) {
    __shared__ float h[8][128], c[8][128], g[8][512], xs[8][8];
    int tid = threadIdx.x;
    for (int i = tid; i < 8 * 128; i += 1024) { ((float*)h)[i] = 0.f; ((float*)c)[i] = 0.f; }
    __syncthreads();
    for (int t = 0; t < T_STEPS; t++) {
        if (tid < 64) xs[tid >> 3][tid & 7] = g_emb[t * 64 + tid];
        __syncthreads();
        #pragma unroll
        for (int task = tid; task < 4096; task += 1024) {
            int b = task >> 9, row = task & 511;
            float acc = b_ih[row] + b_hh[row];
            const float* wi = w_ih + row * 8;
            #pragma unroll
            for (int k = 0; k < 8; k++) acc += xs[b][k] * wi[k];
            const float4* wh = (const float4*)(w_hh + row * 128);
            const float4* hb = (const float4*)h[b];
            #pragma unroll 8
            for (int jj = 0; jj < 32; jj++) {
                float4 w4 = wh[jj], h4 = hb[jj];
                acc = fmaf(w4.x, h4.x, acc); acc = fmaf(w4.y, h4.y, acc);
                acc = fmaf(w4.z, h4.z, acc); acc = fmaf(w4.w, h4.w, acc);
            }
            g[b][row] = acc;
        }
        __syncthreads();
        if (tid < 1024) {
            int b = tid >> 7, u = tid & 127;
            float ig = sigmoidf(g[b][u]);
            float fg = sigmoidf(g[b][128 + u]);
            float gg = tanhf(g[b][256 + u]);
            float og = sigmoidf(g[b][384 + u]);
            float cn = fg * c[b][u] + ig * gg;
            c[b][u] = cn;
            h[b][u] = og * tanhf(cn);
        }
        __syncthreads();
    }
    if (tid < 16) {
        int b = tid >> 1, o = tid & 1;
        float acc = b_fc[o];
        const float* w = w_fc + o * 128;
        #pragma unroll 8
        for (int jj = 0; jj < 128; jj++) acc += h[b][jj] * w[jj];
        out[b * 2 + o] = acc;
    }
}

// ---------------- host launch ----------------
extern "C" void kernel_launch(void* const* d_in, const int* in_sizes, int n_in,
                              void* d_out, int out_size) {
    const float *x_seq = 0, *W1 = 0, *as1 = 0, *ad1 = 0, *b1 = 0;
    const float *W2 = 0, *as2 = 0, *ad2 = 0, *b2 = 0;
    const float *W3 = 0, *as3 = 0, *ad3 = 0, *b3 = 0;
    const float *W4 = 0, *as4 = 0, *ad4 = 0, *b4 = 0;
    const float *w_ih = 0, *w_hh = 0, *b_ih = 0, *b_hh = 0, *w_fc = 0, *b_fc = 0;
    const int *edge = 0;
    int c1024 = 0, c512 = 0, c256 = 0, c128 = 0, c8 = 0;
    for (int i = 0; i < n_in; i++) {
        const float* p = (const float*)d_in[i];
        switch (in_sizes[i]) {
            case 172800: x_seq = p; break;
            case 276480: edge = (const int*)p; break;
            case 8640:   break;
            case 131072: W2 = p; break;
            case 65536:  w_hh = p; break;
            case 32768:  W3 = p; break;
            case 4096:   w_ih = p; break;
            case 1024:   { if (c1024++ == 0) W1 = p; else W4 = p; } break;
            case 512: { int k = c512++;
                if (k == 0) as1 = p; else if (k == 1) ad1 = p; else if (k == 2) b1 = p;
                else if (k == 3) b_ih = p; else b_hh = p; } break;
            case 256: { int k = c256++;
                if (k == 0) as2 = p; else if (k == 1) ad2 = p; else if (k == 2) b2 = p;
                else w_fc = p; } break;
            case 128: { int k = c128++;
                if (k == 0) as3 = p; else if (k == 1) ad3 = p; else b3 = p; } break;
            case 8: { int k = c8++;
                if (k == 0) as4 = p; else if (k == 1) ad4 = p; else b4 = p; } break;
            case 2: b_fc = p; break;
            default: break;
        }
    }
    const int* src = edge;

    float *bufA, *bufB;
    __nv_bfloat16 *X1hi, *X1lo, *Xhi, *Xlo, *W2hi, *W2lo, *W3hi, *W3lo;
    cudaGetSymbolAddress((void**)&bufA, g_bufA);
    cudaGetSymbolAddress((void**)&bufB, g_bufB);
    cudaGetSymbolAddress((void**)&X1hi, g_X1hi);
    cudaGetSymbolAddress((void**)&X1lo, g_X1lo);
    cudaGetSymbolAddress((void**)&Xhi, g_Xhi);
    cudaGetSymbolAddress((void**)&Xlo, g_Xlo);
    cudaGetSymbolAddress((void**)&W2hi, g_W2hi);
    cudaGetSymbolAddress((void**)&W2lo, g_W2lo);
    cudaGetSymbolAddress((void**)&W3hi, g_W3hi);
    cudaGetSymbolAddress((void**)&W3lo, g_W3lo);

    const int SM_L1  = (NPG * 2 + NPG * 8 * 2 + NPG * 16 + 1024 + 512) * 4;
    const int SM_F32 = (NPG * 32 + NPG * 2 + NPG * 17) * 4;
    const int SM_F16 = (NPG * 16 + NPG * 2 + NPG * 17 + NPG * 16) * 4;
    const int SM_F8  = (NPG * 8  + NPG * 2 + NPG * 17 + NPG * 16) * 4;
    cudaFuncSetAttribute(l1_fused, cudaFuncAttributeMaxDynamicSharedMemorySize, SM_L1);
    cudaFuncSetAttribute(fused_gat<8, 32, false, true>, cudaFuncAttributeMaxDynamicSharedMemorySize, SM_F32);
    cudaFuncSetAttribute(fused_gat<8, 16, true, false>, cudaFuncAttributeMaxDynamicSharedMemorySize, SM_F16);
    cudaFuncSetAttribute(fused_gat<1, 8, true, false>,  cudaFuncAttributeMaxDynamicSharedMemorySize, SM_F8);

    // 1: merged setup
    setup_all<<<1181, 256>>>(src, W2, W3, W1, as1, ad1);
    // 2: layer 1 fused -> X1 split bf16
    l1_fused<<<T_STEPS * B_GR, 1024, SM_L1>>>(x_seq, W1, b1);
    // 3: L2 GEMM bf16x3 + cp.async pipeline
    gemm_bf16<<<dim3(2, TN / 128), 512>>>(X1hi, X1lo, W2hi, W2lo, bufA, 512, 256);
    // 4 (PROFILED): GAT layer 2
    fused_gat<8, 32, false, true><<<T_STEPS * B_GR * 8, 1024, SM_F32>>>(bufA, as2, ad2, b2, nullptr);
    // 5: L3 GEMM
    gemm_bf16<<<dim3(1, TN / 128), 512>>>(Xhi, Xlo, W3hi, W3lo, bufA, 256, 128);
    // 6: GAT layer 3
    fused_gat<8, 16, true, false><<<T_STEPS * B_GR * 8, 1024, SM_F16>>>(bufA, as3, ad3, b3, bufB);
    // 7: L4 GEMM fp32
    gemm_l4<<<(TN * 8 + 255) / 256, 256>>>(bufB, W4, bufA);
    // 8: GAT layer 4
    fused_gat<1, 8, true, false><<<T_STEPS * B_GR, 1024, SM_F8>>>(bufA, as4, ad4, b4, bufB);
    // 9-10: pool + LSTM
    pool_kernel<<<T_STEPS * B_GR, 256>>>(bufB);
    lstm_fc<<<1, 1024>>>(w_ih, w_hh, b_ih, b_hh, w_fc, b_fc, (float*)d_out);
}

// round 10
// speedup vs baseline: 1.2891x; 1.0566x over previous
#include <cuda_runtime.h>
#include <cuda_bf16.h>
#include <math.h>

#define T_STEPS 10
#define B_GR    8
#define NPG     1080
#define N_NODES 8640
#define TN      86400
#define DEG     16

// ---------------- scratch ----------------
__device__ float g_bufA[(size_t)TN * 256];
__device__ float g_bufB[(size_t)TN * 256];
__device__ float g_z[TN * 16];
__device__ __nv_bfloat16 g_W2hi[512 * 256], g_W2lo[512 * 256];
__device__ __nv_bfloat16 g_W3hi[256 * 128], g_W3lo[256 * 128];
__device__ float g_emb[T_STEPS * B_GR * 8];
__device__ float g_uv[32];
__device__ int   g_lsrc[N_NODES * 16];

__device__ __forceinline__ void split_bf16(float x, __nv_bfloat16& h, __nv_bfloat16& l) {
    h = __float2bfloat16_rn(x);
    l = __float2bfloat16_rn(x - __bfloat162float(h));
}

// ---------------- fast exp for x <= 0 ----------------
__device__ __forceinline__ float exp_neg(float x) {
    x = fmaxf(x, -87.0f);
    const float L2E = 1.4426950408889634f;
    float z = fmaf(x, L2E, 12582912.0f);
    int   ei = __float_as_int(z);
    float n = z - 12582912.0f;
    float f = fmaf(x, L2E, -n);
    float r = fmaf(1.5403530e-4f, f, 1.3333558e-3f);
    r = fmaf(r, f, 9.6181291e-3f);
    r = fmaf(r, f, 5.5504109e-2f);
    r = fmaf(r, f, 2.4022651e-1f);
    r = fmaf(r, f, 6.9314718e-1f);
    r = fmaf(r, f, 1.0f);
    float s = __int_as_float((ei + 127) << 23);
    return r * s;
}
__device__ __forceinline__ float elu_f(float v) { return v > 0.f ? v : exp_neg(v) - 1.f; }
__device__ __forceinline__ float lrelu(float e) { return e >= 0.f ? e : 0.2f * e; }

// ---------------- setup ----------------
__global__ void setup_lsrc(const int* __restrict__ src) {
    int i = blockIdx.x * 256 + threadIdx.x;
    int b = i / (NPG * 16);
    g_lsrc[i] = src[i] - b * NPG;
}

__global__ void setup_w(const float* __restrict__ W2, const float* __restrict__ W3,
                        const float* __restrict__ W1, const float* __restrict__ as1,
                        const float* __restrict__ ad1) {
    int bid = blockIdx.x, tid = threadIdx.x;
    if (bid < 512) {
        int i = bid * 256 + tid;
        split_bf16(W2[i], g_W2hi[i], g_W2lo[i]);
    } else if (bid < 640) {
        int i = (bid - 512) * 256 + tid;
        split_bf16(W3[i], g_W3hi[i], g_W3lo[i]);
    } else if (tid < 32) {
        int d = tid >> 4, h = (tid >> 1) & 7, f = tid & 1;
        const float* a = d ? ad1 : as1;
        float s = 0.f;
        #pragma unroll
        for (int c = 0; c < 64; c++) s += W1[f * 512 + h * 64 + c] * a[h * 64 + c];
        g_uv[tid] = s;
    }
}

// ---------------- layer 1: x -> z[TN,16] only (640 blocks) ----------------
__global__ __launch_bounds__(256)
void l1_z(const float* __restrict__ x) {
    __shared__ float xs[NPG * 2];
    __shared__ float es_s[NPG * 8];
    __shared__ float uvS[32];
    int blk = blockIdx.x;
    int chunk = blk & 7;
    int tb = blk >> 3;
    int b = tb & 7, t = tb >> 3;
    int base = t * N_NODES + b * NPG;
    int tid = threadIdx.x;
    if (tid < 32) uvS[tid] = g_uv[tid];
    for (int i = tid; i < NPG * 2; i += 256) xs[i] = x[(size_t)base * 2 + i];
    __syncthreads();
    for (int task = tid; task < NPG * 8; task += 256) {
        int n = task >> 3, h = task & 7;
        es_s[task] = fmaf(xs[n * 2], uvS[h * 2], xs[n * 2 + 1] * uvS[h * 2 + 1]);
    }
    __syncthreads();
    int n0 = chunk * 135;
    for (int task = tid; task < 135 * 8; task += 256) {
        int nl = task >> 3, h = task & 7;
        int n = n0 + nl;
        const int4* ls4 = (const int4*)(g_lsrc + ((size_t)b * NPG + n) * 16);
        int4 iA = ls4[0], iB = ls4[1], iC = ls4[2], iD = ls4[3];
        int idxs[16] = {iA.x, iA.y, iA.z, iA.w, iB.x, iB.y, iB.z, iB.w,
                        iC.x, iC.y, iC.z, iC.w, iD.x, iD.y, iD.z, iD.w};
        float ed = fmaf(xs[n * 2], uvS[16 + h * 2], xs[n * 2 + 1] * uvS[17 + h * 2]);
        float ev[17];
        float m = -1e30f;
        #pragma unroll
        for (int k = 0; k < 16; k++) {
            float e = lrelu(es_s[idxs[k] * 8 + h] + ed);
            ev[k] = e; m = fmaxf(m, e);
        }
        { float e = lrelu(es_s[n * 8 + h] + ed); ev[16] = e; m = fmaxf(m, e); }
        float ssum = 0.f;
        #pragma unroll
        for (int k = 0; k < 17; k++) { float v = exp_neg(ev[k] - m); ev[k] = v; ssum += v; }
        float inv = 1.f / (ssum + 1e-16f);
        float z0 = 0.f, z1 = 0.f;
        #pragma unroll
        for (int k = 0; k < 16; k++) {
            float a = ev[k] * inv;
            z0 = fmaf(a, xs[idxs[k] * 2], z0);
            z1 = fmaf(a, xs[idxs[k] * 2 + 1], z1);
        }
        {
            float a = ev[16] * inv;
            z0 = fmaf(a, xs[n * 2], z0);
            z1 = fmaf(a, xs[n * 2 + 1], z1);
        }
        *(float2*)&g_z[(size_t)(base + n) * 16 + h * 2] = make_float2(z0, z1);
    }
}

// ---------------- GEMM shared macros ----------------
#define MMA_BF16(d, a, b0, b1) \
    asm volatile("mma.sync.aligned.m16n8k16.row.col.f32.bf16.bf16.f32 " \
        "{%0,%1,%2,%3}, {%4,%5,%6,%7}, {%8,%9}, {%0,%1,%2,%3};" \
        : "+f"(d[0]), "+f"(d[1]), "+f"(d[2]), "+f"(d[3]) \
        : "r"(a[0]), "r"(a[1]), "r"(a[2]), "r"(a[3]), "r"(b0), "r"(b1))

#define LDMX4(r, addr) \
    asm volatile("ldmatrix.sync.aligned.m8n8.x4.shared.b16 {%0,%1,%2,%3}, [%4];" \
        : "=r"(r[0]), "=r"(r[1]), "=r"(r[2]), "=r"(r[3]) : "r"(addr))

#define LDMX4T(r, addr) \
    asm volatile("ldmatrix.sync.aligned.m8n8.x4.trans.shared.b16 {%0,%1,%2,%3}, [%4];" \
        : "=r"(r[0]), "=r"(r[1]), "=r"(r[2]), "=r"(r[3]) : "r"(addr))

#define CP16(dst, src) \
    asm volatile("cp.async.cg.shared.global [%0], [%1], 16;" :: "r"(dst), "l"(src))
#define CP_COMMIT asm volatile("cp.async.commit_group;")
#define CP_WAIT1  asm volatile("cp.async.wait_group 1;")
#define CP_WAIT0  asm volatile("cp.async.wait_group 0;")

#define ASTR 24
#define BSTR2 136

struct alignas(8) US4 { unsigned short v[4]; };

// ---------------- L2 GEMM with A generated from z (elu(z@W1bd+b1)) ----------------
__global__ __launch_bounds__(512)
void l1gemm_bf16(const float* __restrict__ W1, const float* __restrict__ b1,
                 const __nv_bfloat16* __restrict__ Whi, const __nv_bfloat16* __restrict__ Wlo,
                 float* __restrict__ C) {
    const int Nc = 256;
    __shared__ alignas(16) unsigned short sA[2][128 * ASTR];   // [hi/lo]
    __shared__ alignas(16) unsigned short sB[3][2][16 * BSTR2];
    __shared__ float zs[128][16];
    __shared__ float W1s[1024], b1s[512];
    const int tid = threadIdx.x;
    const int lane = tid & 31, wid = tid >> 5;
    const int warpM = wid & 3, warpN = wid >> 2;
    const int rb = blockIdx.y * 128, cb = blockIdx.x * 128;
    const int hl = tid >> 8;
    const int j = tid & 255;
    const int brow = j >> 4, bcol = (j & 15) * 8;
    const __nv_bfloat16* bptr = (hl ? Wlo : Whi) + (size_t)brow * Nc + cb + bcol;
    unsigned sb_dst[3];
    #pragma unroll
    for (int s = 0; s < 3; s++)
        sb_dst[s] = (unsigned)__cvta_generic_to_shared(&sB[s][hl][brow * BSTR2 + bcol]);
    // stage z, W1, b1
    {
        int row = tid >> 2, q = tid & 3;
        *(float4*)&zs[row][q * 4] = *(const float4*)(g_z + (size_t)(rb + row) * 16 + q * 4);
    }
    for (int i = tid; i < 1024; i += 512) W1s[i] = W1[i];
    if (tid < 512) b1s[tid] = b1[tid];
    CP16(sb_dst[0], bptr);
    CP_COMMIT;
    CP16(sb_dst[1], bptr + (size_t)16 * Nc);
    CP_COMMIT;
    __syncthreads();

    const int arow = tid >> 2, ac0 = (tid & 3) * 4;
    const int a_r = (lane & 15);
    const int a_c = (lane >> 4) * 8;
    const int b_k = (lane & 7) + (lane & 8);
    const int b_n = (lane & 16) >> 1;
    float acc[2][4][4] = {};
    const int nk = 32;

    for (int ck = 0; ck < nk; ck++) {
        // compute A(ck) tile -> sA (single buffer; protected by the 2 syncs)
        {
            int h = ck >> 2;
            float z0 = zs[arow][h * 2], z1 = zs[arow][h * 2 + 1];
            US4 hv, lv;
            #pragma unroll
            for (int i = 0; i < 4; i++) {
                int k = ck * 16 + ac0 + i;
                float v = elu_f(fmaf(z0, W1s[k], fmaf(z1, W1s[512 + k], b1s[k])));
                __nv_bfloat16 bh, bl;
                split_bf16(v, bh, bl);
                hv.v[i] = *(unsigned short*)&bh;
                lv.v[i] = *(unsigned short*)&bl;
            }
            *(US4*)&sA[0][arow * ASTR + ac0] = hv;
            *(US4*)&sA[1][arow * ASTR + ac0] = lv;
        }
        if (ck + 1 < nk) { CP_WAIT1; } else { CP_WAIT0; }
        __syncthreads();
        if (ck + 2 < nk) {
            int buf = (ck + 2) % 3;
            CP16(sb_dst[buf], bptr + (size_t)((ck + 2) * 16) * Nc);
            CP_COMMIT;
        }
        int p = ck % 3;
        unsigned ah[2][4], al[2][4];
        #pragma unroll
        for (int ma = 0; ma < 2; ma++) {
            int r = warpM * 32 + ma * 16 + a_r;
            unsigned adh = (unsigned)__cvta_generic_to_shared(&sA[0][r * ASTR + a_c]);
            unsigned adl = (unsigned)__cvta_generic_to_shared(&sA[1][r * ASTR + a_c]);
            LDMX4(ah[ma], adh);
            LDMX4(al[ma], adl);
        }
        unsigned bh[4][2], bl[4][2];
        #pragma unroll
        for (int g = 0; g < 2; g++) {
            int n0 = warpN * 32 + g * 16 + b_n;
            unsigned adh = (unsigned)__cvta_generic_to_shared(&sB[p][0][b_k * BSTR2 + n0]);
            unsigned adl = (unsigned)__cvta_generic_to_shared(&sB[p][1][b_k * BSTR2 + n0]);
            unsigned th[4], tl[4];
            LDMX4T(th, adh);
            LDMX4T(tl, adl);
            bh[g * 2][0] = th[0]; bh[g * 2][1] = th[1];
            bh[g * 2 + 1][0] = th[2]; bh[g * 2 + 1][1] = th[3];
            bl[g * 2][0] = tl[0]; bl[g * 2][1] = tl[1];
            bl[g * 2 + 1][0] = tl[2]; bl[g * 2 + 1][1] = tl[3];
        }
        #pragma unroll
        for (int ma = 0; ma < 2; ma++)
            #pragma unroll
            for (int na = 0; na < 4; na++) {
                MMA_BF16(acc[ma][na], ah[ma], bh[na][0], bh[na][1]);
                MMA_BF16(acc[ma][na], ah[ma], bl[na][0], bl[na][1]);
                MMA_BF16(acc[ma][na], al[ma], bh[na][0], bh[na][1]);
            }
        __syncthreads();
    }
    #pragma unroll
    for (int ma = 0; ma < 2; ma++)
        #pragma unroll
        for (int na = 0; na < 4; na++) {
            int r0 = rb + warpM * 32 + ma * 16 + (lane >> 2);
            int c = cb + warpN * 32 + na * 8 + (lane & 3) * 2;
            *(float2*)(C + (size_t)r0 * Nc + c)       = make_float2(acc[ma][na][0], acc[ma][na][1]);
            *(float2*)(C + (size_t)(r0 + 8) * Nc + c) = make_float2(acc[ma][na][2], acc[ma][na][3]);
        }
}

// ---------------- L3 GEMM: fp32 A split during staging ----------------
__global__ __launch_bounds__(512)
void gemm3_bf16(const float* __restrict__ A,
                const __nv_bfloat16* __restrict__ Whi, const __nv_bfloat16* __restrict__ Wlo,
                float* __restrict__ C) {
    const int K = 256, Nc = 128;
    __shared__ alignas(16) unsigned short sA[2][128 * ASTR];
    __shared__ alignas(16) unsigned short sB[3][2][16 * BSTR2];
    const int tid = threadIdx.x;
    const int lane = tid & 31, wid = tid >> 5;
    const int warpM = wid & 3, warpN = wid >> 2;
    const int rb = blockIdx.y * 128, cb = 0;
    const int hl = tid >> 8;
    const int j = tid & 255;
    const int brow = j >> 4, bcol = (j & 15) * 8;
    const __nv_bfloat16* bptr = (hl ? Wlo : Whi) + (size_t)brow * Nc + bcol;
    unsigned sb_dst[3];
    #pragma unroll
    for (int s = 0; s < 3; s++)
        sb_dst[s] = (unsigned)__cvta_generic_to_shared(&sB[s][hl][brow * BSTR2 + bcol]);
    const int arow = tid >> 2, ac0 = (tid & 3) * 4;
    const float* aptr = A + (size_t)(rb + arow) * K + ac0;
    CP16(sb_dst[0], bptr);
    CP_COMMIT;
    CP16(sb_dst[1], bptr + (size_t)16 * Nc);
    CP_COMMIT;
    float4 areg = *(const float4*)(aptr);
    const int a_r = (lane & 15);
    const int a_c = (lane >> 4) * 8;
    const int b_k = (lane & 7) + (lane & 8);
    const int b_n = (lane & 16) >> 1;
    float acc[2][4][4] = {};
    const int nk = 16;

    for (int ck = 0; ck < nk; ck++) {
        {
            US4 hv, lv;
            float vals[4] = {areg.x, areg.y, areg.z, areg.w};
            #pragma unroll
            for (int i = 0; i < 4; i++) {
                __nv_bfloat16 bh, bl;
                split_bf16(vals[i], bh, bl);
                hv.v[i] = *(unsigned short*)&bh;
                lv.v[i] = *(unsigned short*)&bl;
            }
            *(US4*)&sA[0][arow * ASTR + ac0] = hv;
            *(US4*)&sA[1][arow * ASTR + ac0] = lv;
        }
        if (ck + 1 < nk) { CP_WAIT1; } else { CP_WAIT0; }
        __syncthreads();
        if (ck + 1 < nk) areg = *(const float4*)(aptr + (ck + 1) * 16);
        if (ck + 2 < nk) {
            int buf = (ck + 2) % 3;
            CP16(sb_dst[buf], bptr + (size_t)((ck + 2) * 16) * Nc);
            CP_COMMIT;
        }
        int p = ck % 3;
        unsigned ah[2][4], al[2][4];
        #pragma unroll
        for (int ma = 0; ma < 2; ma++) {
            int r = warpM * 32 + ma * 16 + a_r;
            unsigned adh = (unsigned)__cvta_generic_to_shared(&sA[0][r * ASTR + a_c]);
            unsigned adl = (unsigned)__cvta_generic_to_shared(&sA[1][r * ASTR + a_c]);
            LDMX4(ah[ma], adh);
            LDMX4(al[ma], adl);
        }
        // warpN in 0..3 but Nc=128 -> warp tile 32 cols; cb=0
        unsigned bh[4][2], bl[4][2];
        #pragma unroll
        for (int g = 0; g < 2; g++) {
            int n0 = warpN * 32 + g * 16 + b_n;
            unsigned adh = (unsigned)__cvta_generic_to_shared(&sB[p][0][b_k * BSTR2 + n0]);
            unsigned adl = (unsigned)__cvta_generic_to_shared(&sB[p][1][b_k * BSTR2 + n0]);
            unsigned th[4], tl[4];
            LDMX4T(th, adh);
            LDMX4T(tl, adl);
            bh[g * 2][0] = th[0]; bh[g * 2][1] = th[1];
            bh[g * 2 + 1][0] = th[2]; bh[g * 2 + 1][1] = th[3];
            bl[g * 2][0] = tl[0]; bl[g * 2][1] = tl[1];
            bl[g * 2 + 1][0] = tl[2]; bl[g * 2 + 1][1] = tl[3];
        }
        #pragma unroll
        for (int ma = 0; ma < 2; ma++)
            #pragma unroll
            for (int na = 0; na < 4; na++) {
                MMA_BF16(acc[ma][na], ah[ma], bh[na][0], bh[na][1]);
                MMA_BF16(acc[ma][na], ah[ma], bl[na][0], bl[na][1]);
                MMA_BF16(acc[ma][na], al[ma], bh[na][0], bh[na][1]);
            }
        __syncthreads();
    }
    #pragma unroll
    for (int ma = 0; ma < 2; ma++)
        #pragma unroll
        for (int na = 0; na < 4; na++) {
            int r0 = rb + warpM * 32 + ma * 16 + (lane >> 2);
            int c = cb + warpN * 32 + na * 8 + (lane & 3) * 2;
            *(float2*)(C + (size_t)r0 * Nc + c)       = make_float2(acc[ma][na][0], acc[ma][na][1]);
            *(float2*)(C + (size_t)(r0 + 8) * Nc + c) = make_float2(acc[ma][na][2], acc[ma][na][3]);
        }
}

// ---------------- L4 GEMM (fp32, tiny) ----------------
__global__ void gemm_l4(const float* __restrict__ X, const float* __restrict__ W4,
                        float* __restrict__ Y) {
    __shared__ float w[1024];
    int tid = threadIdx.x;
    for (int i = tid; i < 1024; i += blockDim.x) w[i] = W4[i];
    __syncthreads();
    int idx = blockIdx.x * blockDim.x + tid;
    if (idx >= TN * 8) return;
    int row = idx >> 3, j = idx & 7;
    const float4* xr = (const float4*)(X + (size_t)row * 128);
    float acc = 0.f;
    #pragma unroll 8
    for (int k = 0; k < 32; k++) {
        float4 v = xr[k];
        acc = fmaf(v.x, w[(k * 4 + 0) * 8 + j], acc);
        acc = fmaf(v.y, w[(k * 4 + 1) * 8 + j], acc);
        acc = fmaf(v.z, w[(k * 4 + 2) * 8 + j], acc);
        acc = fmaf(v.w, w[(k * 4 + 3) * 8 + j], acc);
    }
    Y[idx] = acc;
}

// ---------------- fully fused GAT (fp32 out) ----------------
template<int H, int C, bool LSRC_SMEM>
__global__ __launch_bounds__(1024, 1)
void fused_gat(const float* __restrict__ Y, const float* __restrict__ as_,
               const float* __restrict__ ad_, const float* __restrict__ bias,
               float* __restrict__ Xout) {
    extern __shared__ float sm[];
    constexpr int HC = H * C;
    constexpr int Q = C / 4;
    float* tile   = sm;
    float* es_s   = tile + NPG * C;
    float* ed_s   = es_s + NPG;
    float* alphaS = ed_s + NPG;
    int*   lsrcS  = (int*)(alphaS + NPG * 17);
    __shared__ float as_s[C], ad_s[C], bi_s[C];
    int blk = blockIdx.x;
    int h = (H == 1) ? 0 : (blk % H);
    int tb = (H == 1) ? blk : (blk / H);
    int b = tb % B_GR;
    int t = tb / B_GR;
    int base = t * N_NODES + b * NPG;
    int tid = threadIdx.x;
    const int* lg = g_lsrc + (size_t)b * NPG * 16;
    if (tid < C) { as_s[tid] = as_[h * C + tid]; ad_s[tid] = ad_[h * C + tid]; bi_s[tid] = bias[h * C + tid]; }
    for (int i = tid; i < NPG * Q; i += blockDim.x) {
        int n = i / Q, q = i % Q;
        *(float4*)&tile[n * C + q * 4] =
            *(const float4*)(Y + (size_t)(base + n) * HC + h * C + q * 4);
    }
    if (LSRC_SMEM) {
        for (int i = tid; i < NPG * 4; i += blockDim.x)
            ((int4*)lsrcS)[i] = ((const int4*)lg)[i];
    }
    __syncthreads();
    for (int n = tid; n < NPG; n += blockDim.x) {
        const float* tn = tile + n * C;
        int rot1 = tid & (Q - 1);
        float se = 0.f, de = 0.f;
        #pragma unroll
        for (int jj = 0; jj < Q; jj++) {
            int q = (jj + rot1) & (Q - 1);
            float4 v = *(const float4*)&tn[q * 4];
            float4 a = *(const float4*)&as_s[q * 4];
            float4 d = *(const float4*)&ad_s[q * 4];
            se = fmaf(v.x, a.x, fmaf(v.y, a.y, fmaf(v.z, a.z, fmaf(v.w, a.w, se))));
            de = fmaf(v.x, d.x, fmaf(v.y, d.y, fmaf(v.z, d.z, fmaf(v.w, d.w, de))));
        }
        es_s[n] = se; ed_s[n] = de;
    }
    __syncthreads();
    for (int n = tid; n < NPG; n += blockDim.x) {
        const int4* ls4 = LSRC_SMEM ? (const int4*)(lsrcS + n * 16)
                                    : (const int4*)(lg + n * 16);
        int4 iA = ls4[0], iB = ls4[1], iC_ = ls4[2], iD = ls4[3];
        int idxs[16] = {iA.x, iA.y, iA.z, iA.w, iB.x, iB.y, iB.z, iB.w,
                        iC_.x, iC_.y, iC_.z, iC_.w, iD.x, iD.y, iD.z, iD.w};
        float ed = ed_s[n];
        float m = lrelu(es_s[n] + ed);
        #pragma unroll
        for (int k = 0; k < 16; k++) m = fmaxf(m, lrelu(es_s[idxs[k]] + ed));
        float* ap = alphaS + n * 17;
        float ssum = 0.f;
        #pragma unroll
        for (int k = 0; k < 16; k++) {
            float v = exp_neg(lrelu(es_s[idxs[k]] + ed) - m);
            ap[k] = v; ssum += v;
        }
        { float v = exp_neg(lrelu(es_s[n] + ed) - m); ap[16] = v; ssum += v; }
        float inv = 1.f / (ssum + 1e-16f);
        #pragma unroll
        for (int k = 0; k < 17; k++) ap[k] *= inv;
    }
    __syncthreads();
    for (int task = tid; task < NPG * Q; task += blockDim.x) {
        int n = task / Q, q = task % Q;
        const float* ap = alphaS + n * 17;
        const int* ls = LSRC_SMEM ? (lsrcS + n * 16) : (lg + n * 16);
        float4 acc = make_float4(0.f, 0.f, 0.f, 0.f);
        #pragma unroll
        for (int k = 0; k < 16; k++) {
            int idx = ls[k];
            float a = ap[k];
            float4 v = *(const float4*)&tile[idx * C + q * 4];
            acc.x = fmaf(a, v.x, acc.x); acc.y = fmaf(a, v.y, acc.y);
            acc.z = fmaf(a, v.z, acc.z); acc.w = fmaf(a, v.w, acc.w);
        }
        {
            float a = ap[16];
            float4 v = *(const float4*)&tile[n * C + q * 4];
            acc.x = fmaf(a, v.x, acc.x); acc.y = fmaf(a, v.y, acc.y);
            acc.z = fmaf(a, v.z, acc.z); acc.w = fmaf(a, v.w, acc.w);
        }
        float4 o;
        o.x = elu_f(acc.x + bi_s[q * 4 + 0]);
        o.y = elu_f(acc.y + bi_s[q * 4 + 1]);
        o.z = elu_f(acc.z + bi_s[q * 4 + 2]);
        o.w = elu_f(acc.w + bi_s[q * 4 + 3]);
        *(float4*)(Xout + (size_t)(base + n) * HC + h * C + q * 4) = o;
    }
}

// ---------------- mean pool ----------------
__global__ void pool_kernel(const float* __restrict__ X4) {
    int tb = blockIdx.x;
    int t = tb / B_GR, b = tb % B_GR;
    int tid = threadIdx.x;
    float acc[8] = {};
    for (int nn = tid; nn < NPG; nn += blockDim.x) {
        const float* p = X4 + ((size_t)(t * N_NODES + b * NPG + nn)) * 8;
        #pragma unroll
        for (int f = 0; f < 8; f++) acc[f] += p[f];
    }
    __shared__ float s[8];
    if (tid < 8) s[tid] = 0.f;
    __syncthreads();
    #pragma unroll
    for (int f = 0; f < 8; f++) atomicAdd(&s[f], acc[f]);
    __syncthreads();
    if (tid < 8) g_emb[tb * 8 + tid] = s[tid] * (1.0f / (float)NPG);
}

// ---------------- LSTM + FC ----------------
__device__ __forceinline__ float sigmoidf(float x) { return 1.f / (1.f + expf(-x)); }

__global__ void lstm_fc(const float* __restrict__ w_ih, const float* __restrict__ w_hh,
                        const float* __restrict__ b_ih, const float* __restrict__ b_hh,
                        const float* __restrict__ w_fc, const float* __restrict__ b_fc,
                        float* __restrict__ out) {
    __shared__ float h[8][128], c[8][128], g[8][512], xs[8][8];
    int tid = threadIdx.x;
    for (int i = tid; i < 8 * 128; i += 1024) { ((float*)h)[i] = 0.f; ((float*)c)[i] = 0.f; }
    __syncthreads();
    for (int t = 0; t < T_STEPS; t++) {
        if (tid < 64) xs[tid >> 3][tid & 7] = g_emb[t * 64 + tid];
        __syncthreads();
        #pragma unroll
        for (int task = tid; task < 4096; task += 1024) {
            int b = task >> 9, row = task & 511;
            float acc = b_ih[row] + b_hh[row];
            const float* wi = w_ih + row * 8;
            #pragma unroll
            for (int k = 0; k < 8; k++) acc += xs[b][k] * wi[k];
            const float4* wh = (const float4*)(w_hh + row * 128);
            const float4* hb = (const float4*)h[b];
            #pragma unroll 8
            for (int jj = 0; jj < 32; jj++) {
                float4 w4 = wh[jj], h4 = hb[jj];
                acc = fmaf(w4.x, h4.x, acc); acc = fmaf(w4.y, h4.y, acc);
                acc = fmaf(w4.z, h4.z, acc); acc = fmaf(w4.w, h4.w, acc);
            }
            g[b][row] = acc;
        }
        __syncthreads();
        if (tid < 1024) {
            int b = tid >> 7, u = tid & 127;
            float ig = sigmoidf(g[b][u]);
            float fg = sigmoidf(g[b][128 + u]);
            float gg = tanhf(g[b][256 + u]);
            float og = sigmoidf(g[b][384 + u]);
            float cn = fg * c[b][u] + ig * gg;
            c[b][u] = cn;
            h[b][u] = og * tanhf(cn);
        }
        __syncthreads();
    }
    if (tid < 16) {
        int b = tid >> 1, o = tid & 1;
        float acc = b_fc[o];
        const float* w = w_fc + o * 128;
        #pragma unroll 8
        for (int jj = 0; jj < 128; jj++) acc += h[b][jj] * w[jj];
        out[b * 2 + o] = acc;
    }
}

// ---------------- host launch ----------------
extern "C" void kernel_launch(void* const* d_in, const int* in_sizes, int n_in,
                              void* d_out, int out_size) {
    const float *x_seq = 0, *W1 = 0, *as1 = 0, *ad1 = 0, *b1 = 0;
    const float *W2 = 0, *as2 = 0, *ad2 = 0, *b2 = 0;
    const float *W3 = 0, *as3 = 0, *ad3 = 0, *b3 = 0;
    const float *W4 = 0, *as4 = 0, *ad4 = 0, *b4 = 0;
    const float *w_ih = 0, *w_hh = 0, *b_ih = 0, *b_hh = 0, *w_fc = 0, *b_fc = 0;
    const int *edge = 0;
    int c1024 = 0, c512 = 0, c256 = 0, c128 = 0, c8 = 0;
    for (int i = 0; i < n_in; i++) {
        const float* p = (const float*)d_in[i];
        switch (in_sizes[i]) {
            case 172800: x_seq = p; break;
            case 276480: edge = (const int*)p; break;
            case 8640:   break;
            case 131072: W2 = p; break;
            case 65536:  w_hh = p; break;
            case 32768:  W3 = p; break;
            case 4096:   w_ih = p; break;
            case 1024:   { if (c1024++ == 0) W1 = p; else W4 = p; } break;
            case 512: { int k = c512++;
                if (k == 0) as1 = p; else if (k == 1) ad1 = p; else if (k == 2) b1 = p;
                else if (k == 3) b_ih = p; else b_hh = p; } break;
            case 256: { int k = c256++;
                if (k == 0) as2 = p; else if (k == 1) ad2 = p; else if (k == 2) b2 = p;
                else w_fc = p; } break;
            case 128: { int k = c128++;
                if (k == 0) as3 = p; else if (k == 1) ad3 = p; else b3 = p; } break;
            case 8: { int k = c8++;
                if (k == 0) as4 = p; else if (k == 1) ad4 = p; else b4 = p; } break;
            case 2: b_fc = p; break;
            default: break;
        }
    }
    const int* src = edge;

    float *bufA, *bufB;
    __nv_bfloat16 *W2hi, *W2lo, *W3hi, *W3lo;
    cudaGetSymbolAddress((void**)&bufA, g_bufA);
    cudaGetSymbolAddress((void**)&bufB, g_bufB);
    cudaGetSymbolAddress((void**)&W2hi, g_W2hi);
    cudaGetSymbolAddress((void**)&W2lo, g_W2lo);
    cudaGetSymbolAddress((void**)&W3hi, g_W3hi);
    cudaGetSymbolAddress((void**)&W3lo, g_W3lo);

    const int SM_F32 = (NPG * 32 + NPG * 2 + NPG * 17) * 4;
    const int SM_F16 = (NPG * 16 + NPG * 2 + NPG * 17 + NPG * 16) * 4;
    const int SM_F8  = (NPG * 8  + NPG * 2 + NPG * 17 + NPG * 16) * 4;
    cudaFuncSetAttribute(fused_gat<8, 32, false>, cudaFuncAttributeMaxDynamicSharedMemorySize, SM_F32);
    cudaFuncSetAttribute(fused_gat<8, 16, true>,  cudaFuncAttributeMaxDynamicSharedMemorySize, SM_F16);
    cudaFuncSetAttribute(fused_gat<1, 8, true>,   cudaFuncAttributeMaxDynamicSharedMemorySize, SM_F8);

    // 1: localize src
    setup_lsrc<<<540, 256>>>(src);
    // 2: W splits + uvec
    setup_w<<<641, 256>>>(W2, W3, W1, as1, ad1);
    // 3: layer-1 z
    l1_z<<<640, 256>>>(x_seq);
    // 4 (PROFILED): L2 GEMM with fused L1 expansion (tensor cores)
    l1gemm_bf16<<<dim3(2, TN / 128), 512>>>(W1, b1, W2hi, W2lo, bufA);
    // 5: GAT layer 2 (fp32 out)
    fused_gat<8, 32, false><<<T_STEPS * B_GR * 8, 1024, SM_F32>>>(bufA, as2, ad2, b2, bufB);
    // 6: L3 GEMM (fp32 A split in staging)
    gemm3_bf16<<<dim3(1, TN / 128), 512>>>(bufB, W3hi, W3lo, bufA);
    // 7: GAT layer 3
    fused_gat<8, 16, true><<<T_STEPS * B_GR * 8, 1024, SM_F16>>>(bufA, as3, ad3, b3, bufB);
    // 8: L4 GEMM fp32
    gemm_l4<<<(TN * 8 + 255) / 256, 256>>>(bufB, W4, bufA);
    // 9: GAT layer 4
    fused_gat<1, 8, true><<<T_STEPS * B_GR, 1024, SM_F8>>>(bufA, as4, ad4, b4, bufB);
    // 10-11: pool + LSTM
    pool_kernel<<<T_STEPS * B_GR, 256>>>(bufB);
    lstm_fc<<<1, 1024>>>(w_ih, w_hh, b_ih, b_hh, w_fc, b_fc, (float*)d_out);
}